// round 3
// baseline (speedup 1.0000x reference)
#include <cuda_runtime.h>

#define B_   64
#define T_   13
#define N_   325
#define H_   64
#define C_   4
#define S_   4
#define P_   12
#define NB_  1300
#define OFF_ 975
#define NH_  (N_*H_)        // 20800
#define BNH_ (B_*NH_)       // 1331200

// ---------------- scratch (device globals; no runtime alloc allowed) --------
__device__ float  g_gf  [BNH_];
__device__ float  g_res [BNH_];
__device__ float  g_h3  [BNH_];
__device__ float  g_cr  [BNH_];
__device__ float  g_last[BNH_];
__device__ float  g_H0  [2][C_][BNH_];   // layer-0 outputs per (mat, channel)
__device__ float  g_C1  [2][C_][BNH_];   // layer-1 outputs (ca / cp)
__device__ float  g_Wsum[2][C_][2][H_*H_];
__device__ int    g_cols[2][N_][N_];
__device__ float  g_vals[2][N_][N_];
__device__ int    g_cnt [2][N_];
__device__ double g_sums[2];

// ---------------- prep: Wsum[mat][c][l] = W[c,l,0] + W[c,l,1] ---------------
__global__ void k_wsum(const float* __restrict__ aw, const float* __restrict__ pw) {
    int idx = blockIdx.x * blockDim.x + threadIdx.x;   // 65536 total
    if (idx >= 2 * C_ * 2 * H_ * H_) return;
    int mat = idx >> 15;
    int r   = idx & 32767;
    int c   = r >> 13;
    int l   = (r >> 12) & 1;
    int e   = r & 4095;
    const float* src = mat ? pw : aw;
    int base = ((c * 2 + l) * 2) * 4096;               // [c][l][j][k][h]
    ((float*)g_Wsum)[idx] = src[base + e] + src[base + 4096 + e];
}

// ---------------- prep: compact nonzeros of the last diagonal block ---------
__global__ void k_compact(const float* __restrict__ adjf, const float* __restrict__ peaf) {
    int rowid = blockIdx.x;            // 0..2*N_-1
    int mat = rowid / N_;
    int n   = rowid % N_;
    const float* A = mat ? peaf : adjf;
    int lane = threadIdx.x;
    int cnt = 0;
    for (int base = 0; base < N_; base += 32) {
        int m = base + lane;
        float w = (m < N_) ? A[(long)(OFF_ + n) * NB_ + OFF_ + m] : 0.f;
        unsigned mask = __ballot_sync(0xffffffffu, w != 0.f);
        if (w != 0.f) {
            int pos = cnt + __popc(mask & ((1u << lane) - 1u));
            g_cols[mat][n][pos] = m;
            g_vals[mat][n][pos] = w;
        }
        cnt += __popc(mask);
    }
    if (lane == 0) g_cnt[mat][n] = cnt;
}

// ---------------- per-checkpoint: gf / residual / h3 (x computed inline) ----
__global__ void k_A(const float* __restrict__ inp, const float* __restrict__ w_in,
                    const float* __restrict__ b_in, const float* __restrict__ res_w,
                    const float* __restrict__ res_b, const float* __restrict__ gcw,
                    const float* __restrict__ gcb, int ck, int left) {
    int idx = blockIdx.x * blockDim.x + threadIdx.x;
    if (idx >= BNH_) return;
    if (idx == 0) { g_sums[0] = 0.0; g_sums[1] = 0.0; }
    int h = idx & 63;
    int n = (idx >> 6) % N_;
    int b = idx / NH_;
    float w0 = w_in[h], w1 = w_in[64 + h], bi = b_in[h];
    float gf = 0.f, rs = 0.f, v = 0.f;
#pragma unroll
    for (int s = 0; s < 4; ++s) {
        if (ck > 0 && s == 0) {
            v = g_last[idx];
        } else {
            int t = (ck == 0) ? s : (left + s - 1);
            const float* ip = inp + (((long)b * T_ + t) * N_ + n) * 2;
            v = ip[0] * w0 + ip[1] * w1 + bi;
        }
        gf += gcw[s] * v;
        rs += res_w[s] * v;
    }
    g_gf[idx]  = gf + gcb[0];
    g_res[idx] = rs + res_b[0];
    g_h3[idx]  = v;   // slice s=3
}

// ---------------- GCN layer 0: m0 = adj @ h3 (shared), then 4 channel GEMMs -
__global__ void k_layer0(int mat, const float* __restrict__ gb) {
    __shared__ float sm[16][64];
    int n  = blockIdx.x;
    int bg = blockIdx.y;               // 16-batch group
    int t  = threadIdx.x;
    int hd = t & 63;
    int lq = t >> 6;                   // 0..3
    int cnt = g_cnt[mat][n];
    const int*   cols = g_cols[mat][n];
    const float* vals = g_vals[mat][n];
    int b0 = bg * 16 + lq * 4;
    float acc[4] = {0.f, 0.f, 0.f, 0.f};
    for (int i = 0; i < cnt; ++i) {
        int m = cols[i];
        float w = vals[i];
        const float* hp = g_h3 + m * 64 + hd;
#pragma unroll
        for (int j = 0; j < 4; ++j) acc[j] += w * hp[(b0 + j) * NH_];
    }
#pragma unroll
    for (int j = 0; j < 4; ++j) sm[lq * 4 + j][hd] = acc[j];
    __syncthreads();
#pragma unroll
    for (int c = 0; c < C_; ++c) {
        const float* W = g_Wsum[mat][c][0];
        float bias = gb[(c * 2 + 0) * 64 + hd];
        float out[4] = {bias, bias, bias, bias};
        for (int kk = 0; kk < 64; ++kk) {
            float wv = __ldg(&W[kk * 64 + hd]);
#pragma unroll
            for (int j = 0; j < 4; ++j) out[j] += sm[lq * 4 + j][kk] * wv;
        }
#pragma unroll
        for (int j = 0; j < 4; ++j) {
            float o = out[j] > 0.f ? out[j] : 0.f;
            g_H0[mat][c][(b0 + j) * NH_ + n * 64 + hd] = o;
        }
    }
}

// ---------------- GCN layer 1: per-channel SpMM + GEMM ----------------------
__global__ void k_layer1(int mat, const float* __restrict__ gb) {
    __shared__ float sm[16][64];
    int n  = blockIdx.x;
    int bg = blockIdx.y;
    int c  = blockIdx.z;
    int t  = threadIdx.x;
    int hd = t & 63;
    int lq = t >> 6;
    int cnt = g_cnt[mat][n];
    const int*   cols = g_cols[mat][n];
    const float* vals = g_vals[mat][n];
    const float* hsrc = g_H0[mat][c];
    int b0 = bg * 16 + lq * 4;
    float acc[4] = {0.f, 0.f, 0.f, 0.f};
    for (int i = 0; i < cnt; ++i) {
        int m = cols[i];
        float w = vals[i];
        const float* hp = hsrc + m * 64 + hd;
#pragma unroll
        for (int j = 0; j < 4; ++j) acc[j] += w * hp[(b0 + j) * NH_];
    }
#pragma unroll
    for (int j = 0; j < 4; ++j) sm[lq * 4 + j][hd] = acc[j];
    __syncthreads();
    const float* W = g_Wsum[mat][c][1];
    float bias = gb[(c * 2 + 1) * 64 + hd];
    float out[4] = {bias, bias, bias, bias};
    for (int kk = 0; kk < 64; ++kk) {
        float wv = __ldg(&W[kk * 64 + hd]);
#pragma unroll
        for (int j = 0; j < 4; ++j) out[j] += sm[lq * 4 + j][kk] * wv;
    }
#pragma unroll
    for (int j = 0; j < 4; ++j) {
        float o = out[j] > 0.f ? out[j] : 0.f;
        g_C1[mat][c][(b0 + j) * NH_ + n * 64 + hd] = o;
    }
}

// ---------------- gate -> combine -> reduce -> +residual --------------------
__global__ void k_gate(const float* __restrict__ g1w, const float* __restrict__ g1b,
                       const float* __restrict__ g2w, const float* __restrict__ g2b,
                       const float* __restrict__ rw,  const float* __restrict__ rb) {
    __shared__ float sh_in[4][64];
    __shared__ float sh_g1[4][64];
    __shared__ float sh_gr[4][256];
    int t  = threadIdx.x;
    int h  = t & 63;
    int rl = t >> 6;
    int row = blockIdx.x * 4 + rl;     // (b,n) flattened, 20800 rows
    int base = row * 64;
    sh_in[rl][h] = g_gf[base + h];
    __syncthreads();
    float a = g1b[h];
    for (int k = 0; k < 64; ++k) a += sh_in[rl][k] * __ldg(&g1w[k * 64 + h]);
    sh_g1[rl][h] = a > 0.f ? a : 0.f;
    __syncthreads();
#pragma unroll
    for (int q = 0; q < 4; ++q) {
        int h2 = q * 64 + h;
        float s = g2b[h2];
        for (int k = 0; k < 64; ++k) s += sh_g1[rl][k] * __ldg(&g2w[k * 256 + h2]);
        float gate = 1.f / (1.f + expf(-s));
        float ca  = g_C1[0][q][base + h];
        float cpv = g_C1[1][q][base + h];
        sh_gr[rl][h2] = gate * ca + (1.f - gate) * cpv;
    }
    __syncthreads();
    float o = rb[h];
    for (int k = 0; k < 256; ++k) o += sh_gr[rl][k] * __ldg(&rw[k * 64 + h]);
    g_cr[base + h] = o + g_res[base + h];
}

// ---------------- global mean/var reduction ---------------------------------
__global__ void k_sum() {
    __shared__ double ss[256], sq[256];
    double s = 0.0, q = 0.0;
    for (int i = blockIdx.x * blockDim.x + threadIdx.x; i < BNH_;
         i += gridDim.x * blockDim.x) {
        double v = (double)g_cr[i];
        s += v; q += v * v;
    }
    ss[threadIdx.x] = s; sq[threadIdx.x] = q;
    __syncthreads();
    for (int o = 128; o > 0; o >>= 1) {
        if (threadIdx.x < o) {
            ss[threadIdx.x] += ss[threadIdx.x + o];
            sq[threadIdx.x] += sq[threadIdx.x + o];
        }
        __syncthreads();
    }
    if (threadIdx.x == 0) {
        atomicAdd(&g_sums[0], ss[0]);
        atomicAdd(&g_sums[1], sq[0]);
    }
}

// ---------------- whole-tensor layernorm ------------------------------------
__global__ void k_norm() {
    __shared__ float s_mu, s_r;
    if (threadIdx.x == 0) {
        double mu  = g_sums[0] / (double)BNH_;
        double var = g_sums[1] / (double)BNH_ - mu * mu;
        s_mu = (float)mu;
        s_r  = (float)rsqrt(var + 1e-5);
    }
    __syncthreads();
    int i = blockIdx.x * blockDim.x + threadIdx.x;
    if (i < BNH_) g_last[i] = (g_cr[i] - s_mu) * s_r;
}

// ---------------- final: 1x1 conv over P + linear H->1 ----------------------
__global__ void k_out(const float* __restrict__ cw, const float* __restrict__ cb,
                      const float* __restrict__ lw, const float* __restrict__ lb,
                      float* __restrict__ out) {
    __shared__ float red[4][2];
    int t = threadIdx.x;
    int h = t & 63;
    int rl = t >> 6;
    int row = blockIdx.x * 4 + rl;     // (b,n)
    int b = row / N_, n = row % N_;
    float v   = g_last[row * 64 + h];
    float lin = lw[h];
    int lane = t & 31;
    int w2   = (t >> 5) & 1;
    for (int p = 0; p < P_; ++p) {
        float x = cw[p] * v + cb[p];
        x = x > 0.f ? x : 0.f;
        float s = x * lin;
#pragma unroll
        for (int o = 16; o > 0; o >>= 1) s += __shfl_down_sync(0xffffffffu, s, o);
        if (lane == 0) red[rl][w2] = s;
        __syncthreads();
        if (h == 0) out[((long)b * P_ + p) * N_ + n] = red[rl][0] + red[rl][1] + lb[0];
        __syncthreads();
    }
}

// ---------------- launcher ---------------------------------------------------
extern "C" void kernel_launch(void* const* d_in, const int* in_sizes, int n_in,
                              void* d_out, int out_size) {
    const float* inputs    = (const float*)d_in[0];
    const float* adj_fwd   = (const float*)d_in[1];
    const float* pea_fwd   = (const float*)d_in[3];
    const float* w_in      = (const float*)d_in[5];
    const float* b_in      = (const float*)d_in[6];
    const float* res_w     = (const float*)d_in[7];
    const float* res_b     = (const float*)d_in[8];
    const float* gconv_w   = (const float*)d_in[9];
    const float* gconv_b   = (const float*)d_in[10];
    const float* gate1_w   = (const float*)d_in[11];
    const float* gate1_b   = (const float*)d_in[12];
    const float* gate2_w   = (const float*)d_in[13];
    const float* gate2_b   = (const float*)d_in[14];
    const float* reduce_w  = (const float*)d_in[15];
    const float* reduce_b  = (const float*)d_in[16];
    const float* gcn_adj_w = (const float*)d_in[17];
    const float* gcn_adj_b = (const float*)d_in[18];
    const float* gcn_pea_w = (const float*)d_in[19];
    const float* gcn_pea_b = (const float*)d_in[20];
    const float* out_cw    = (const float*)d_in[21];
    const float* out_cb    = (const float*)d_in[22];
    const float* out_lw    = (const float*)d_in[23];
    const float* out_lb    = (const float*)d_in[24];
    float* out = (float*)d_out;

    k_wsum<<<256, 256>>>(gcn_adj_w, gcn_pea_w);
    k_compact<<<2 * N_, 32>>>(adj_fwd, pea_fwd);

    const int lefts[4] = {0, 4, 7, 10};
    for (int ck = 0; ck < 4; ++ck) {
        k_A<<<BNH_ / 256, 256>>>(inputs, w_in, b_in, res_w, res_b,
                                 gconv_w, gconv_b, ck, lefts[ck]);
        dim3 gl0(N_, 4);
        k_layer0<<<gl0, 256>>>(0, gcn_adj_b);
        k_layer0<<<gl0, 256>>>(1, gcn_pea_b);
        dim3 gl1(N_, 4, C_);
        k_layer1<<<gl1, 256>>>(0, gcn_adj_b);
        k_layer1<<<gl1, 256>>>(1, gcn_pea_b);
        k_gate<<<BNH_ / 64 / 4, 256>>>(gate1_w, gate1_b, gate2_w, gate2_b,
                                       reduce_w, reduce_b);
        k_sum<<<512, 256>>>();
        k_norm<<<BNH_ / 256, 256>>>();
    }
    k_out<<<(B_ * N_) / 4, 256>>>(out_cw, out_cb, out_lw, out_lb, out);
}

// round 4
// speedup vs baseline: 1.2226x; 1.2226x over previous
#include <cuda_runtime.h>

#define B_   64
#define T_   13
#define N_   325
#define H_   64
#define C_   4
#define S_   4
#define P_   12
#define NB_  1300
#define OFF_ 975
#define NH_  (N_*H_)        // 20800
#define BNH_ (B_*NH_)       // 1331200

// ---------------- scratch (device globals; no runtime alloc allowed) --------
__device__ float  g_gf  [BNH_];
__device__ float  g_res [BNH_];
__device__ float  g_h3  [BNH_];
__device__ float  g_cr  [BNH_];
__device__ float  g_H0  [2][C_][BNH_];   // layer-0 outputs per (mat, channel)
__device__ float  g_C1  [2][C_][BNH_];   // layer-1 outputs (ca / cp)
__device__ float  g_Wsum[2][C_][2][H_*H_];
__device__ int    g_cols[2][N_][N_];
__device__ float  g_vals[2][N_][N_];
__device__ int    g_cnt [2][N_];
__device__ double g_sumsA[4][2];         // per-checkpoint (sum, sumsq)

// ---------------- prep: Wsum[mat][c][l] = W[c,l,0] + W[c,l,1]; zero sums ----
__global__ void k_wsum(const float* __restrict__ aw, const float* __restrict__ pw) {
    int idx = blockIdx.x * blockDim.x + threadIdx.x;   // 65536 total
    if (idx < 8) ((double*)g_sumsA)[idx] = 0.0;
    if (idx >= 2 * C_ * 2 * H_ * H_) return;
    int mat = idx >> 15;
    int r   = idx & 32767;
    int c   = r >> 13;
    int l   = (r >> 12) & 1;
    int e   = r & 4095;
    const float* src = mat ? pw : aw;
    int base = ((c * 2 + l) * 2) * 4096;               // [c][l][j][k][h]
    ((float*)g_Wsum)[idx] = src[base + e] + src[base + 4096 + e];
}

// ---------------- prep: compact nonzeros of the last diagonal block ---------
__global__ void k_compact(const float* __restrict__ adjf, const float* __restrict__ peaf) {
    int rowid = blockIdx.x;            // 0..2*N_-1
    int mat = rowid / N_;
    int n   = rowid % N_;
    const float* A = mat ? peaf : adjf;
    int lane = threadIdx.x;
    int cnt = 0;
    for (int base = 0; base < N_; base += 32) {
        int m = base + lane;
        float w = (m < N_) ? A[(long)(OFF_ + n) * NB_ + OFF_ + m] : 0.f;
        unsigned mask = __ballot_sync(0xffffffffu, w != 0.f);
        if (w != 0.f) {
            int pos = cnt + __popc(mask & ((1u << lane) - 1u));
            g_cols[mat][n][pos] = m;
            g_vals[mat][n][pos] = w;
        }
        cnt += __popc(mask);
    }
    if (lane == 0) g_cnt[mat][n] = cnt;
}

// ---------------- per-checkpoint: gf / residual / h3 (x + norm inline) ------
__global__ void k_A(const float* __restrict__ inp, const float* __restrict__ w_in,
                    const float* __restrict__ b_in, const float* __restrict__ res_w,
                    const float* __restrict__ res_b, const float* __restrict__ gcw,
                    const float* __restrict__ gcb, int ck, int left) {
    __shared__ float s_mu, s_r;
    if (threadIdx.x == 0) {
        if (ck > 0) {
            double mu  = g_sumsA[ck - 1][0] / (double)BNH_;
            double var = g_sumsA[ck - 1][1] / (double)BNH_ - mu * mu;
            s_mu = (float)mu;
            s_r  = (float)rsqrt(var + 1e-5);
        } else { s_mu = 0.f; s_r = 0.f; }
    }
    __syncthreads();
    int idx = blockIdx.x * blockDim.x + threadIdx.x;
    if (idx >= BNH_) return;
    int h = idx & 63;
    int n = (idx >> 6) % N_;
    int b = idx / NH_;
    float w0 = w_in[h], w1 = w_in[64 + h], bi = b_in[h];
    float gf = 0.f, rs = 0.f, v = 0.f;
#pragma unroll
    for (int s = 0; s < 4; ++s) {
        if (ck > 0 && s == 0) {
            v = (g_cr[idx] - s_mu) * s_r;
        } else {
            int t = (ck == 0) ? s : (left + s - 1);
            const float2 ip = *(const float2*)(inp + (((long)b * T_ + t) * N_ + n) * 2);
            v = ip.x * w0 + ip.y * w1 + bi;
        }
        gf += gcw[s] * v;
        rs += res_w[s] * v;
    }
    g_gf[idx]  = gf + gcb[0];
    g_res[idx] = rs + res_b[0];
    g_h3[idx]  = v;   // slice s=3
}

// ---------------- GCN layer 0: SpMM (float4, smem-indexed) + 4 GEMMs --------
__global__ void k_layer0(const float* __restrict__ gbA, const float* __restrict__ gbP) {
    __shared__ int   scols[328];
    __shared__ float svals[328];
    __shared__ float sm[16][64];
    int n   = blockIdx.x;
    int bg  = blockIdx.y;
    int mat = blockIdx.z;
    int t   = threadIdx.x;
    int cnt = g_cnt[mat][n];
    for (int i = t; i < cnt; i += 256) {
        scols[i] = g_cols[mat][n][i];
        svals[i] = g_vals[mat][n][i];
    }
    __syncthreads();

    int b0 = bg * 16;
    {   // SpMM: thread = (batch b, h-quad hq)
        int b  = t >> 4;
        int hq = t & 15;
        const float4* hp = (const float4*)(g_h3 + (long)(b0 + b) * NH_) + hq;
        float4 acc = make_float4(0.f, 0.f, 0.f, 0.f);
        int i = 0;
        for (; i + 2 <= cnt; i += 2) {
            int   m0 = scols[i],   m1 = scols[i + 1];
            float w0 = svals[i],   w1 = svals[i + 1];
            float4 v0 = hp[m0 * 16];
            float4 v1 = hp[m1 * 16];
            acc.x = fmaf(w0, v0.x, acc.x); acc.y = fmaf(w0, v0.y, acc.y);
            acc.z = fmaf(w0, v0.z, acc.z); acc.w = fmaf(w0, v0.w, acc.w);
            acc.x = fmaf(w1, v1.x, acc.x); acc.y = fmaf(w1, v1.y, acc.y);
            acc.z = fmaf(w1, v1.z, acc.z); acc.w = fmaf(w1, v1.w, acc.w);
        }
        if (i < cnt) {
            float w = svals[i];
            float4 v = hp[scols[i] * 16];
            acc.x = fmaf(w, v.x, acc.x); acc.y = fmaf(w, v.y, acc.y);
            acc.z = fmaf(w, v.z, acc.z); acc.w = fmaf(w, v.w, acc.w);
        }
        ((float4*)sm)[b * 16 + hq] = acc;
    }
    __syncthreads();

    int h  = t & 63;
    int bq = t >> 6;
    const float* gb = mat ? gbP : gbA;
#pragma unroll
    for (int c = 0; c < C_; ++c) {
        const float* W = g_Wsum[mat][c][0];
        float bias = gb[(c * 2 + 0) * 64 + h];
        float out[4] = {bias, bias, bias, bias};
        for (int k = 0; k < 64; ++k) {
            float wv = __ldg(&W[k * 64 + h]);
#pragma unroll
            for (int j = 0; j < 4; ++j) out[j] = fmaf(sm[bq * 4 + j][k], wv, out[j]);
        }
#pragma unroll
        for (int j = 0; j < 4; ++j) {
            float o = out[j] > 0.f ? out[j] : 0.f;
            g_H0[mat][c][(long)(b0 + bq * 4 + j) * NH_ + n * 64 + h] = o;
        }
    }
}

// ---------------- GCN layer 1: all 4 channels fused per block ---------------
__global__ void k_layer1(const float* __restrict__ gbA, const float* __restrict__ gbP) {
    __shared__ int   scols[328];
    __shared__ float svals[328];
    __shared__ float smc[C_][16][64];
    int n   = blockIdx.x;
    int bg  = blockIdx.y;
    int mat = blockIdx.z;
    int t   = threadIdx.x;
    int cnt = g_cnt[mat][n];
    for (int i = t; i < cnt; i += 256) {
        scols[i] = g_cols[mat][n][i];
        svals[i] = g_vals[mat][n][i];
    }
    __syncthreads();

    int b0 = bg * 16;
    {   // SpMM over 4 channels simultaneously: 4 independent gather streams
        int b  = t >> 4;
        int hq = t & 15;
        long boff = (long)(b0 + b) * NH_;
        const float4* hp0 = (const float4*)(g_H0[mat][0] + boff) + hq;
        const float4* hp1 = (const float4*)(g_H0[mat][1] + boff) + hq;
        const float4* hp2 = (const float4*)(g_H0[mat][2] + boff) + hq;
        const float4* hp3 = (const float4*)(g_H0[mat][3] + boff) + hq;
        float4 a0 = make_float4(0.f,0.f,0.f,0.f), a1 = a0, a2 = a0, a3 = a0;
        for (int i = 0; i < cnt; ++i) {
            int   mo = scols[i] * 16;
            float w  = svals[i];
            float4 v0 = hp0[mo];
            float4 v1 = hp1[mo];
            float4 v2 = hp2[mo];
            float4 v3 = hp3[mo];
            a0.x = fmaf(w, v0.x, a0.x); a0.y = fmaf(w, v0.y, a0.y);
            a0.z = fmaf(w, v0.z, a0.z); a0.w = fmaf(w, v0.w, a0.w);
            a1.x = fmaf(w, v1.x, a1.x); a1.y = fmaf(w, v1.y, a1.y);
            a1.z = fmaf(w, v1.z, a1.z); a1.w = fmaf(w, v1.w, a1.w);
            a2.x = fmaf(w, v2.x, a2.x); a2.y = fmaf(w, v2.y, a2.y);
            a2.z = fmaf(w, v2.z, a2.z); a2.w = fmaf(w, v2.w, a2.w);
            a3.x = fmaf(w, v3.x, a3.x); a3.y = fmaf(w, v3.y, a3.y);
            a3.z = fmaf(w, v3.z, a3.z); a3.w = fmaf(w, v3.w, a3.w);
        }
        ((float4*)smc[0])[b * 16 + hq] = a0;
        ((float4*)smc[1])[b * 16 + hq] = a1;
        ((float4*)smc[2])[b * 16 + hq] = a2;
        ((float4*)smc[3])[b * 16 + hq] = a3;
    }
    __syncthreads();

    int h  = t & 63;
    int bq = t >> 6;
    const float* gb = mat ? gbP : gbA;
#pragma unroll
    for (int c = 0; c < C_; ++c) {
        const float* W = g_Wsum[mat][c][1];
        float bias = gb[(c * 2 + 1) * 64 + h];
        float out[4] = {bias, bias, bias, bias};
        for (int k = 0; k < 64; ++k) {
            float wv = __ldg(&W[k * 64 + h]);
#pragma unroll
            for (int j = 0; j < 4; ++j) out[j] = fmaf(smc[c][bq * 4 + j][k], wv, out[j]);
        }
#pragma unroll
        for (int j = 0; j < 4; ++j) {
            float o = out[j] > 0.f ? out[j] : 0.f;
            g_C1[mat][c][(long)(b0 + bq * 4 + j) * NH_ + n * 64 + h] = o;
        }
    }
}

// ------- gate -> combine -> reduce -> +residual, fused LN partial sums ------
__global__ void k_gate(const float* __restrict__ g1w, const float* __restrict__ g1b,
                       const float* __restrict__ g2w, const float* __restrict__ g2b,
                       const float* __restrict__ rw,  const float* __restrict__ rb,
                       int ck) {
    __shared__ float sh_in[16][64];
    __shared__ float sh_g1[16][64];
    __shared__ float sh_gr[16][256];
    __shared__ double reds[8], redq[8];
    int t   = threadIdx.x;
    int h   = t & 63;
    int rq  = t >> 6;                  // 0..3, 4 rows each
    int row0 = blockIdx.x * 16;

#pragma unroll
    for (int j = 0; j < 4; ++j)
        sh_in[rq * 4 + j][h] = g_gf[(row0 + rq * 4 + j) * 64 + h];
    __syncthreads();

    // stage 1: relu(gf @ g1w + g1b)
    {
        float b1 = g1b[h];
        float a[4] = {b1, b1, b1, b1};
        for (int k = 0; k < 64; ++k) {
            float wv = __ldg(&g1w[k * 64 + h]);
#pragma unroll
            for (int j = 0; j < 4; ++j) a[j] = fmaf(sh_in[rq * 4 + j][k], wv, a[j]);
        }
#pragma unroll
        for (int j = 0; j < 4; ++j)
            sh_g1[rq * 4 + j][h] = a[j] > 0.f ? a[j] : 0.f;
    }
    __syncthreads();

    // stage 2: sigmoid(g1 @ g2w + g2b), blend ca/cp
#pragma unroll
    for (int q = 0; q < 4; ++q) {
        int h2 = q * 64 + h;
        float b2 = g2b[h2];
        float s[4] = {b2, b2, b2, b2};
        for (int k = 0; k < 64; ++k) {
            float wv = __ldg(&g2w[k * 256 + h2]);
#pragma unroll
            for (int j = 0; j < 4; ++j) s[j] = fmaf(sh_g1[rq * 4 + j][k], wv, s[j]);
        }
#pragma unroll
        for (int j = 0; j < 4; ++j) {
            int rr = row0 + rq * 4 + j;
            float gate = 1.f / (1.f + expf(-s[j]));
            float ca   = g_C1[0][q][(long)rr * 64 + h];
            float cpv  = g_C1[1][q][(long)rr * 64 + h];
            sh_gr[rq * 4 + j][h2] = gate * ca + (1.f - gate) * cpv;
        }
    }
    __syncthreads();

    // stage 3: gr @ reduce_w + reduce_b + residual, with LN partial sums
    {
        float br = rb[h];
        float o[4] = {br, br, br, br};
        for (int k = 0; k < 256; ++k) {
            float wv = __ldg(&rw[k * 64 + h]);
#pragma unroll
            for (int j = 0; j < 4; ++j) o[j] = fmaf(sh_gr[rq * 4 + j][k], wv, o[j]);
        }
        double ls = 0.0, lq = 0.0;
#pragma unroll
        for (int j = 0; j < 4; ++j) {
            long rr = (long)(row0 + rq * 4 + j) * 64 + h;
            float val = o[j] + g_res[rr];
            g_cr[rr] = val;
            ls += (double)val;
            lq += (double)val * (double)val;
        }
        // block reduce (8 warps)
        for (int off = 16; off > 0; off >>= 1) {
            ls += __shfl_down_sync(0xffffffffu, ls, off);
            lq += __shfl_down_sync(0xffffffffu, lq, off);
        }
        int wid = t >> 5;
        if ((t & 31) == 0) { reds[wid] = ls; redq[wid] = lq; }
        __syncthreads();
        if (wid == 0) {
            ls = (t < 8) ? reds[t] : 0.0;
            lq = (t < 8) ? redq[t] : 0.0;
            for (int off = 4; off > 0; off >>= 1) {
                ls += __shfl_down_sync(0xffffffffu, ls, off);
                lq += __shfl_down_sync(0xffffffffu, lq, off);
            }
            if (t == 0) {
                atomicAdd(&g_sumsA[ck][0], ls);
                atomicAdd(&g_sumsA[ck][1], lq);
            }
        }
    }
}

// ---------------- final: norm inline, 1x1 conv over P + linear H->1 ---------
__global__ void k_out(const float* __restrict__ cw, const float* __restrict__ cb,
                      const float* __restrict__ lw, const float* __restrict__ lb,
                      float* __restrict__ out) {
    __shared__ float red[4][2];
    __shared__ float s_mu, s_r;
    int t = threadIdx.x;
    if (t == 0) {
        double mu  = g_sumsA[3][0] / (double)BNH_;
        double var = g_sumsA[3][1] / (double)BNH_ - mu * mu;
        s_mu = (float)mu;
        s_r  = (float)rsqrt(var + 1e-5);
    }
    __syncthreads();
    int h  = t & 63;
    int rl = t >> 6;
    int row = blockIdx.x * 4 + rl;     // (b,n)
    int b = row / N_, n = row % N_;
    float v   = (g_cr[(long)row * 64 + h] - s_mu) * s_r;
    float lin = lw[h];
    int lane = t & 31;
    int w2   = (t >> 5) & 1;
    for (int p = 0; p < P_; ++p) {
        float x = cw[p] * v + cb[p];
        x = x > 0.f ? x : 0.f;
        float s = x * lin;
#pragma unroll
        for (int o = 16; o > 0; o >>= 1) s += __shfl_down_sync(0xffffffffu, s, o);
        if (lane == 0) red[rl][w2] = s;
        __syncthreads();
        if (h == 0) out[((long)b * P_ + p) * N_ + n] = red[rl][0] + red[rl][1] + lb[0];
        __syncthreads();
    }
}

// ---------------- launcher ---------------------------------------------------
extern "C" void kernel_launch(void* const* d_in, const int* in_sizes, int n_in,
                              void* d_out, int out_size) {
    const float* inputs    = (const float*)d_in[0];
    const float* adj_fwd   = (const float*)d_in[1];
    const float* pea_fwd   = (const float*)d_in[3];
    const float* w_in      = (const float*)d_in[5];
    const float* b_in      = (const float*)d_in[6];
    const float* res_w     = (const float*)d_in[7];
    const float* res_b     = (const float*)d_in[8];
    const float* gconv_w   = (const float*)d_in[9];
    const float* gconv_b   = (const float*)d_in[10];
    const float* gate1_w   = (const float*)d_in[11];
    const float* gate1_b   = (const float*)d_in[12];
    const float* gate2_w   = (const float*)d_in[13];
    const float* gate2_b   = (const float*)d_in[14];
    const float* reduce_w  = (const float*)d_in[15];
    const float* reduce_b  = (const float*)d_in[16];
    const float* gcn_adj_w = (const float*)d_in[17];
    const float* gcn_adj_b = (const float*)d_in[18];
    const float* gcn_pea_w = (const float*)d_in[19];
    const float* gcn_pea_b = (const float*)d_in[20];
    const float* out_cw    = (const float*)d_in[21];
    const float* out_cb    = (const float*)d_in[22];
    const float* out_lw    = (const float*)d_in[23];
    const float* out_lb    = (const float*)d_in[24];
    float* out = (float*)d_out;

    k_wsum<<<256, 256>>>(gcn_adj_w, gcn_pea_w);
    k_compact<<<2 * N_, 32>>>(adj_fwd, pea_fwd);

    const int lefts[4] = {0, 4, 7, 10};
    dim3 gl(N_, 4, 2);
    for (int ck = 0; ck < 4; ++ck) {
        k_A<<<BNH_ / 256, 256>>>(inputs, w_in, b_in, res_w, res_b,
                                 gconv_w, gconv_b, ck, lefts[ck]);
        k_layer0<<<gl, 256>>>(gcn_adj_b, gcn_pea_b);
        k_layer1<<<gl, 256>>>(gcn_adj_b, gcn_pea_b);
        k_gate<<<BNH_ / 64 / 16, 256>>>(gate1_w, gate1_b, gate2_w, gate2_b,
                                        reduce_w, reduce_b, ck);
    }
    k_out<<<(B_ * N_) / 4, 256>>>(out_cw, out_cb, out_lw, out_lb, out);
}

// round 5
// speedup vs baseline: 1.2227x; 1.0001x over previous
#include <cuda_runtime.h>

#define B_   64
#define T_   13
#define N_   325
#define H_   64
#define C_   4
#define S_   4
#define P_   12
#define NB_  1300
#define OFF_ 975
#define NH_  (N_*H_)        // 20800
#define BNH_ (B_*NH_)       // 1331200

// ---------------- scratch (device globals; no runtime alloc allowed) --------
__device__ float  g_gf  [BNH_];
__device__ float  g_res [BNH_];
__device__ float  g_h3  [BNH_];
__device__ float  g_cr  [BNH_];
__device__ float  g_H0  [2][C_][BNH_];
__device__ float  g_C1  [2][C_][BNH_];
__device__ float  g_Wsum[2][C_][2][H_*H_];
__device__ int    g_cols[2][N_][N_];
__device__ float  g_vals[2][N_][N_];
__device__ int    g_cnt [2][N_];
__device__ double g_sumsA[4][2];         // per-checkpoint (sum, sumsq)

// ---------------- prep: Wsum[mat][c][l] = W[c,l,0] + W[c,l,1]; zero sums ----
__global__ void k_wsum(const float* __restrict__ aw, const float* __restrict__ pw) {
    int idx = blockIdx.x * blockDim.x + threadIdx.x;
    if (idx < 8) ((double*)g_sumsA)[idx] = 0.0;
    if (idx >= 2 * C_ * 2 * H_ * H_) return;
    int mat = idx >> 15;
    int r   = idx & 32767;
    int c   = r >> 13;
    int l   = (r >> 12) & 1;
    int e   = r & 4095;
    const float* src = mat ? pw : aw;
    int base = ((c * 2 + l) * 2) * 4096;
    ((float*)g_Wsum)[idx] = src[base + e] + src[base + 4096 + e];
}

// ---------------- prep: compact nonzeros of the last diagonal block ---------
__global__ void k_compact(const float* __restrict__ adjf, const float* __restrict__ peaf) {
    int rowid = blockIdx.x;
    int mat = rowid / N_;
    int n   = rowid % N_;
    const float* A = mat ? peaf : adjf;
    int lane = threadIdx.x;
    int cnt = 0;
    for (int base = 0; base < N_; base += 32) {
        int m = base + lane;
        float w = (m < N_) ? A[(long)(OFF_ + n) * NB_ + OFF_ + m] : 0.f;
        unsigned mask = __ballot_sync(0xffffffffu, w != 0.f);
        if (w != 0.f) {
            int pos = cnt + __popc(mask & ((1u << lane) - 1u));
            g_cols[mat][n][pos] = m;
            g_vals[mat][n][pos] = w;
        }
        cnt += __popc(mask);
    }
    if (lane == 0) g_cnt[mat][n] = cnt;
}

// ---------------- per-checkpoint: gf / residual / h3 (x + norm inline) ------
__global__ void k_A(const float* __restrict__ inp, const float* __restrict__ w_in,
                    const float* __restrict__ b_in, const float* __restrict__ res_w,
                    const float* __restrict__ res_b, const float* __restrict__ gcw,
                    const float* __restrict__ gcb, int ck, int left) {
    __shared__ float s_mu, s_r;
    if (threadIdx.x == 0) {
        if (ck > 0) {
            double mu  = g_sumsA[ck - 1][0] / (double)BNH_;
            double var = g_sumsA[ck - 1][1] / (double)BNH_ - mu * mu;
            s_mu = (float)mu;
            s_r  = (float)rsqrt(var + 1e-5);
        } else { s_mu = 0.f; s_r = 0.f; }
    }
    __syncthreads();
    int idx = blockIdx.x * blockDim.x + threadIdx.x;
    if (idx >= BNH_) return;
    int h = idx & 63;
    int n = (idx >> 6) % N_;
    int b = idx / NH_;
    float w0 = w_in[h], w1 = w_in[64 + h], bi = b_in[h];
    float gf = 0.f, rs = 0.f, v = 0.f;
#pragma unroll
    for (int s = 0; s < 4; ++s) {
        if (ck > 0 && s == 0) {
            v = (g_cr[idx] - s_mu) * s_r;
        } else {
            int t = (ck == 0) ? s : (left + s - 1);
            const float2 ip = *(const float2*)(inp + (((long)b * T_ + t) * N_ + n) * 2);
            v = ip.x * w0 + ip.y * w1 + bi;
        }
        gf += gcw[s] * v;
        rs += res_w[s] * v;
    }
    g_gf[idx]  = gf + gcb[0];
    g_res[idx] = rs + res_b[0];
    g_h3[idx]  = v;
}

// ---------------- helpers ----------------------------------------------------
__device__ __forceinline__ void fma16(float4 acc[4], float a0, float a1, float a2,
                                      float a3, float4 w) {
    acc[0].x = fmaf(a0, w.x, acc[0].x); acc[0].y = fmaf(a0, w.y, acc[0].y);
    acc[0].z = fmaf(a0, w.z, acc[0].z); acc[0].w = fmaf(a0, w.w, acc[0].w);
    acc[1].x = fmaf(a1, w.x, acc[1].x); acc[1].y = fmaf(a1, w.y, acc[1].y);
    acc[1].z = fmaf(a1, w.z, acc[1].z); acc[1].w = fmaf(a1, w.w, acc[1].w);
    acc[2].x = fmaf(a2, w.x, acc[2].x); acc[2].y = fmaf(a2, w.y, acc[2].y);
    acc[2].z = fmaf(a2, w.z, acc[2].z); acc[2].w = fmaf(a2, w.w, acc[2].w);
    acc[3].x = fmaf(a3, w.x, acc[3].x); acc[3].y = fmaf(a3, w.y, acc[3].y);
    acc[3].z = fmaf(a3, w.z, acc[3].z); acc[3].w = fmaf(a3, w.w, acc[3].w);
}
__device__ __forceinline__ float4 relu4(float4 v) {
    v.x = v.x > 0.f ? v.x : 0.f; v.y = v.y > 0.f ? v.y : 0.f;
    v.z = v.z > 0.f ? v.z : 0.f; v.w = v.w > 0.f ? v.w : 0.f;
    return v;
}

// ---------------- GCN layer 0: SpMM (all 64 batches) + 4x4-tiled GEMMs ------
__global__ void __launch_bounds__(256) k_layer0(const float* __restrict__ gbA,
                                                const float* __restrict__ gbP) {
    __shared__ int   scols[336];
    __shared__ float svals[336];
    __shared__ float sA[64][64];      // [batch][k]
    int n   = blockIdx.x;
    int mat = blockIdx.y;
    int t   = threadIdx.x;
    int cnt = g_cnt[mat][n];
    for (int i = t; i < cnt; i += 256) {
        scols[i] = g_cols[mat][n][i];
        svals[i] = g_vals[mat][n][i];
    }
    __syncthreads();

    {   // SpMM: thread = (bq = t>>4 batch-quad, hq = t&15 h-quad)
        int hq = t & 15;
        int bq = t >> 4;
        const float4* h4 = (const float4*)g_h3 + hq;
        float4 a0 = make_float4(0.f,0.f,0.f,0.f), a1 = a0, a2 = a0, a3 = a0;
        long r0 = (long)(bq * 4 + 0) * (NH_ / 4);
        long r1 = r0 + (NH_ / 4), r2 = r1 + (NH_ / 4), r3 = r2 + (NH_ / 4);
        for (int i = 0; i < cnt; ++i) {
            int   mo = scols[i] * 16;
            float w  = svals[i];
            float4 v0 = h4[r0 + mo];
            float4 v1 = h4[r1 + mo];
            float4 v2 = h4[r2 + mo];
            float4 v3 = h4[r3 + mo];
            a0.x = fmaf(w, v0.x, a0.x); a0.y = fmaf(w, v0.y, a0.y);
            a0.z = fmaf(w, v0.z, a0.z); a0.w = fmaf(w, v0.w, a0.w);
            a1.x = fmaf(w, v1.x, a1.x); a1.y = fmaf(w, v1.y, a1.y);
            a1.z = fmaf(w, v1.z, a1.z); a1.w = fmaf(w, v1.w, a1.w);
            a2.x = fmaf(w, v2.x, a2.x); a2.y = fmaf(w, v2.y, a2.y);
            a2.z = fmaf(w, v2.z, a2.z); a2.w = fmaf(w, v2.w, a2.w);
            a3.x = fmaf(w, v3.x, a3.x); a3.y = fmaf(w, v3.y, a3.y);
            a3.z = fmaf(w, v3.z, a3.z); a3.w = fmaf(w, v3.w, a3.w);
        }
        *(float4*)&sA[bq * 4 + 0][hq * 4] = a0;
        *(float4*)&sA[bq * 4 + 1][hq * 4] = a1;
        *(float4*)&sA[bq * 4 + 2][hq * 4] = a2;
        *(float4*)&sA[bq * 4 + 3][hq * 4] = a3;
    }
    __syncthreads();

    int tx = t & 15;                  // h quad
    int ty = t >> 4;                  // batch quad
    const float* gb = mat ? gbP : gbA;
#pragma unroll
    for (int c = 0; c < C_; ++c) {
        const float4* W4 = (const float4*)g_Wsum[mat][c][0] + tx;
        float4 bias = ((const float4*)(gb + (c * 2) * 64))[tx];
        float4 acc[4] = {bias, bias, bias, bias};
        const float* Ar0 = sA[ty * 4 + 0];
        const float* Ar1 = sA[ty * 4 + 1];
        const float* Ar2 = sA[ty * 4 + 2];
        const float* Ar3 = sA[ty * 4 + 3];
#pragma unroll 4
        for (int k = 0; k < 64; ++k) {
            float4 w = __ldg(&W4[k * 16]);
            fma16(acc, Ar0[k], Ar1[k], Ar2[k], Ar3[k], w);
        }
        float* dst = g_H0[mat][c] + n * 64 + tx * 4;
#pragma unroll
        for (int j = 0; j < 4; ++j)
            *(float4*)(dst + (long)(ty * 4 + j) * NH_) = relu4(acc[j]);
    }
}

// ---------------- GCN layer 1: per-channel SpMM + 4x4-tiled GEMM ------------
__global__ void __launch_bounds__(256) k_layer1(const float* __restrict__ gbA,
                                                const float* __restrict__ gbP) {
    __shared__ int   scols[336];
    __shared__ float svals[336];
    __shared__ float sA[64][64];
    int n   = blockIdx.x;
    int mat = blockIdx.y;
    int t   = threadIdx.x;
    int cnt = g_cnt[mat][n];
    for (int i = t; i < cnt; i += 256) {
        scols[i] = g_cols[mat][n][i];
        svals[i] = g_vals[mat][n][i];
    }
    __syncthreads();

    int hq = t & 15, bq = t >> 4;
    int tx = t & 15, ty = t >> 4;
    const float* gb = mat ? gbP : gbA;
#pragma unroll
    for (int c = 0; c < C_; ++c) {
        if (c) __syncthreads();       // previous GEMM done reading sA
        {   // SpMM from H0[mat][c]
            const float4* h4 = (const float4*)g_H0[mat][c] + hq;
            float4 a0 = make_float4(0.f,0.f,0.f,0.f), a1 = a0, a2 = a0, a3 = a0;
            long r0 = (long)(bq * 4 + 0) * (NH_ / 4);
            long r1 = r0 + (NH_ / 4), r2 = r1 + (NH_ / 4), r3 = r2 + (NH_ / 4);
            for (int i = 0; i < cnt; ++i) {
                int   mo = scols[i] * 16;
                float w  = svals[i];
                float4 v0 = h4[r0 + mo];
                float4 v1 = h4[r1 + mo];
                float4 v2 = h4[r2 + mo];
                float4 v3 = h4[r3 + mo];
                a0.x = fmaf(w, v0.x, a0.x); a0.y = fmaf(w, v0.y, a0.y);
                a0.z = fmaf(w, v0.z, a0.z); a0.w = fmaf(w, v0.w, a0.w);
                a1.x = fmaf(w, v1.x, a1.x); a1.y = fmaf(w, v1.y, a1.y);
                a1.z = fmaf(w, v1.z, a1.z); a1.w = fmaf(w, v1.w, a1.w);
                a2.x = fmaf(w, v2.x, a2.x); a2.y = fmaf(w, v2.y, a2.y);
                a2.z = fmaf(w, v2.z, a2.z); a2.w = fmaf(w, v2.w, a2.w);
                a3.x = fmaf(w, v3.x, a3.x); a3.y = fmaf(w, v3.y, a3.y);
                a3.z = fmaf(w, v3.z, a3.z); a3.w = fmaf(w, v3.w, a3.w);
            }
            *(float4*)&sA[bq * 4 + 0][hq * 4] = a0;
            *(float4*)&sA[bq * 4 + 1][hq * 4] = a1;
            *(float4*)&sA[bq * 4 + 2][hq * 4] = a2;
            *(float4*)&sA[bq * 4 + 3][hq * 4] = a3;
        }
        __syncthreads();
        {   // GEMM with Wsum[mat][c][1]
            const float4* W4 = (const float4*)g_Wsum[mat][c][1] + tx;
            float4 bias = ((const float4*)(gb + (c * 2 + 1) * 64))[tx];
            float4 acc[4] = {bias, bias, bias, bias};
            const float* Ar0 = sA[ty * 4 + 0];
            const float* Ar1 = sA[ty * 4 + 1];
            const float* Ar2 = sA[ty * 4 + 2];
            const float* Ar3 = sA[ty * 4 + 3];
#pragma unroll 4
            for (int k = 0; k < 64; ++k) {
                float4 w = __ldg(&W4[k * 16]);
                fma16(acc, Ar0[k], Ar1[k], Ar2[k], Ar3[k], w);
            }
            float* dst = g_C1[mat][c] + n * 64 + tx * 4;
#pragma unroll
            for (int j = 0; j < 4; ++j)
                *(float4*)(dst + (long)(ty * 4 + j) * NH_) = relu4(acc[j]);
        }
    }
}

// ------- gate -> combine -> reduce -> +residual, fused LN partial sums ------
__global__ void __launch_bounds__(256) k_gate(
        const float* __restrict__ g1w, const float* __restrict__ g1b,
        const float* __restrict__ g2w, const float* __restrict__ g2b,
        const float* __restrict__ rw,  const float* __restrict__ rb, int ck) {
    __shared__ float sBuf[64][64];
    __shared__ float sG1[64][64];
    __shared__ double reds[8], redq[8];
    int t = threadIdx.x;
    long row0 = (long)blockIdx.x * 64;

    {   // load gf tile
        float4* d = (float4*)sBuf;
        const float4* s = (const float4*)(g_gf + row0 * 64);
#pragma unroll
        for (int i = 0; i < 4; ++i) d[t + 256 * i] = s[t + 256 * i];
    }
    __syncthreads();

    int tx = t & 15, ty = t >> 4;
    {   // stage 1: relu(gf @ g1w + g1b) -> sG1
        const float4* W4 = (const float4*)g1w + tx;
        float4 b1 = ((const float4*)g1b)[tx];
        float4 acc[4] = {b1, b1, b1, b1};
        const float* A0 = sBuf[ty * 4 + 0];
        const float* A1 = sBuf[ty * 4 + 1];
        const float* A2 = sBuf[ty * 4 + 2];
        const float* A3 = sBuf[ty * 4 + 3];
#pragma unroll 4
        for (int k = 0; k < 64; ++k)
            fma16(acc, A0[k], A1[k], A2[k], A3[k], __ldg(&W4[k * 16]));
#pragma unroll
        for (int j = 0; j < 4; ++j)
            *(float4*)&sG1[ty * 4 + j][tx * 4] = relu4(acc[j]);
    }
    __syncthreads();

    float4 rbv = ((const float4*)rb)[tx];
    float4 acc3[4] = {rbv, rbv, rbv, rbv};
#pragma unroll
    for (int q = 0; q < 4; ++q) {
        // stage 2: sigmoid(sG1 @ g2w[:, q*64:+64] + b2), blend ca/cp
        float4 b2 = ((const float4*)(g2b + q * 64))[tx];
        float4 acc2[4] = {b2, b2, b2, b2};
        {
            const float4* W4 = (const float4*)(g2w + q * 64) + tx;
            const float* A0 = sG1[ty * 4 + 0];
            const float* A1 = sG1[ty * 4 + 1];
            const float* A2 = sG1[ty * 4 + 2];
            const float* A3 = sG1[ty * 4 + 3];
#pragma unroll 4
            for (int k = 0; k < 64; ++k)
                fma16(acc2, A0[k], A1[k], A2[k], A3[k], __ldg(&W4[k * 64]));
        }
        __syncthreads();              // protect sBuf (prev stage-3 reads)
#pragma unroll
        for (int j = 0; j < 4; ++j) {
            long rr = (row0 + ty * 4 + j) * 64 + tx * 4;
            float4 ca = *(const float4*)&g_C1[0][q][rr];
            float4 cp = *(const float4*)&g_C1[1][q][rr];
            float4 g;
            g.x = 1.f / (1.f + expf(-acc2[j].x));
            g.y = 1.f / (1.f + expf(-acc2[j].y));
            g.z = 1.f / (1.f + expf(-acc2[j].z));
            g.w = 1.f / (1.f + expf(-acc2[j].w));
            float4 o;
            o.x = g.x * ca.x + (1.f - g.x) * cp.x;
            o.y = g.y * ca.y + (1.f - g.y) * cp.y;
            o.z = g.z * ca.z + (1.f - g.z) * cp.z;
            o.w = g.w * ca.w + (1.f - g.w) * cp.w;
            *(float4*)&sBuf[ty * 4 + j][tx * 4] = o;
        }
        __syncthreads();
        // stage 3 partial: acc3 += sBuf @ rw[q*64:+64, :]
        {
            const float4* W4 = (const float4*)(rw + (q * 64) * 64) + tx;
            const float* A0 = sBuf[ty * 4 + 0];
            const float* A1 = sBuf[ty * 4 + 1];
            const float* A2 = sBuf[ty * 4 + 2];
            const float* A3 = sBuf[ty * 4 + 3];
#pragma unroll 4
            for (int k = 0; k < 64; ++k)
                fma16(acc3, A0[k], A1[k], A2[k], A3[k], __ldg(&W4[k * 16]));
        }
    }

    // epilogue: + residual, store cr, LN partial sums
    double ls = 0.0, lq = 0.0;
#pragma unroll
    for (int j = 0; j < 4; ++j) {
        long rr = (row0 + ty * 4 + j) * 64 + tx * 4;
        float4 rv = *(const float4*)&g_res[rr];
        float4 v;
        v.x = acc3[j].x + rv.x; v.y = acc3[j].y + rv.y;
        v.z = acc3[j].z + rv.z; v.w = acc3[j].w + rv.w;
        *(float4*)&g_cr[rr] = v;
        ls += (double)v.x + (double)v.y + (double)v.z + (double)v.w;
        lq += (double)v.x * v.x + (double)v.y * v.y +
              (double)v.z * v.z + (double)v.w * v.w;
    }
    for (int off = 16; off > 0; off >>= 1) {
        ls += __shfl_down_sync(0xffffffffu, ls, off);
        lq += __shfl_down_sync(0xffffffffu, lq, off);
    }
    int wid = t >> 5;
    if ((t & 31) == 0) { reds[wid] = ls; redq[wid] = lq; }
    __syncthreads();
    if (wid == 0) {
        ls = (t < 8) ? reds[t] : 0.0;
        lq = (t < 8) ? redq[t] : 0.0;
        for (int off = 4; off > 0; off >>= 1) {
            ls += __shfl_down_sync(0xffffffffu, ls, off);
            lq += __shfl_down_sync(0xffffffffu, lq, off);
        }
        if (t == 0) {
            atomicAdd(&g_sumsA[ck][0], ls);
            atomicAdd(&g_sumsA[ck][1], lq);
        }
    }
}

// ---------------- final: norm inline, 1x1 conv over P + linear H->1 ---------
__global__ void k_out(const float* __restrict__ cw, const float* __restrict__ cb,
                      const float* __restrict__ lw, const float* __restrict__ lb,
                      float* __restrict__ out) {
    __shared__ float red[4][2];
    __shared__ float s_mu, s_r;
    int t = threadIdx.x;
    if (t == 0) {
        double mu  = g_sumsA[3][0] / (double)BNH_;
        double var = g_sumsA[3][1] / (double)BNH_ - mu * mu;
        s_mu = (float)mu;
        s_r  = (float)rsqrt(var + 1e-5);
    }
    __syncthreads();
    int h  = t & 63;
    int rl = t >> 6;
    int row = blockIdx.x * 4 + rl;
    int b = row / N_, n = row % N_;
    float v   = (g_cr[(long)row * 64 + h] - s_mu) * s_r;
    float lin = lw[h];
    int lane = t & 31;
    int w2   = (t >> 5) & 1;
    for (int p = 0; p < P_; ++p) {
        float x = cw[p] * v + cb[p];
        x = x > 0.f ? x : 0.f;
        float s = x * lin;
#pragma unroll
        for (int o = 16; o > 0; o >>= 1) s += __shfl_down_sync(0xffffffffu, s, o);
        if (lane == 0) red[rl][w2] = s;
        __syncthreads();
        if (h == 0) out[((long)b * P_ + p) * N_ + n] = red[rl][0] + red[rl][1] + lb[0];
        __syncthreads();
    }
}

// ---------------- launcher ---------------------------------------------------
extern "C" void kernel_launch(void* const* d_in, const int* in_sizes, int n_in,
                              void* d_out, int out_size) {
    const float* inputs    = (const float*)d_in[0];
    const float* adj_fwd   = (const float*)d_in[1];
    const float* pea_fwd   = (const float*)d_in[3];
    const float* w_in      = (const float*)d_in[5];
    const float* b_in      = (const float*)d_in[6];
    const float* res_w     = (const float*)d_in[7];
    const float* res_b     = (const float*)d_in[8];
    const float* gconv_w   = (const float*)d_in[9];
    const float* gconv_b   = (const float*)d_in[10];
    const float* gate1_w   = (const float*)d_in[11];
    const float* gate1_b   = (const float*)d_in[12];
    const float* gate2_w   = (const float*)d_in[13];
    const float* gate2_b   = (const float*)d_in[14];
    const float* reduce_w  = (const float*)d_in[15];
    const float* reduce_b  = (const float*)d_in[16];
    const float* gcn_adj_w = (const float*)d_in[17];
    const float* gcn_adj_b = (const float*)d_in[18];
    const float* gcn_pea_w = (const float*)d_in[19];
    const float* gcn_pea_b = (const float*)d_in[20];
    const float* out_cw    = (const float*)d_in[21];
    const float* out_cb    = (const float*)d_in[22];
    const float* out_lw    = (const float*)d_in[23];
    const float* out_lb    = (const float*)d_in[24];
    float* out = (float*)d_out;

    k_wsum<<<256, 256>>>(gcn_adj_w, gcn_pea_w);
    k_compact<<<2 * N_, 32>>>(adj_fwd, pea_fwd);

    const int lefts[4] = {0, 4, 7, 10};
    dim3 gl(N_, 2);
    for (int ck = 0; ck < 4; ++ck) {
        k_A<<<BNH_ / 256, 256>>>(inputs, w_in, b_in, res_w, res_b,
                                 gconv_w, gconv_b, ck, lefts[ck]);
        k_layer0<<<gl, 256>>>(gcn_adj_b, gcn_pea_b);
        k_layer1<<<gl, 256>>>(gcn_adj_b, gcn_pea_b);
        k_gate<<<BNH_ / 64 / 64, 256>>>(gate1_w, gate1_b, gate2_w, gate2_b,
                                        reduce_w, reduce_b, ck);
    }
    k_out<<<(B_ * N_) / 4, 256>>>(out_cw, out_cb, out_lw, out_lb, out);
}

// round 6
// speedup vs baseline: 1.3081x; 1.0698x over previous
#include <cuda_runtime.h>

#define B_   64
#define T_   13
#define N_   325
#define H_   64
#define C_   4
#define S_   4
#define P_   12
#define NB_  1300
#define OFF_ 975
#define NH_  (N_*H_)        // 20800
#define BNH_ (B_*NH_)       // 1331200

typedef unsigned long long u64;

// ---------------- scratch (device globals; no runtime alloc allowed) --------
__device__ float  g_gf  [BNH_];
__device__ float  g_res [BNH_];
__device__ float  g_h3  [BNH_];
__device__ float  g_cr  [BNH_];
__device__ float  g_H0  [2][C_][BNH_];
__device__ float  g_C1  [2][C_][BNH_];
__device__ float  g_Wsum[2][C_][2][H_*H_];
__device__ int    g_cols[2][N_][N_];
__device__ float  g_vals[2][N_][N_];
__device__ int    g_cnt [2][N_];
__device__ double g_sumsA[4][2];         // per-checkpoint (sum, sumsq)

// ---------------- f32x2 packed helpers --------------------------------------
__device__ __forceinline__ u64 pack2(float x, float y) {
    u64 r;
    asm("mov.b64 %0, {%1, %2};" : "=l"(r) : "f"(x), "f"(y));
    return r;
}
__device__ __forceinline__ float2 unpack2(u64 v) {
    float2 r;
    asm("mov.b64 {%0, %1}, %2;" : "=f"(r.x), "=f"(r.y) : "l"(v));
    return r;
}
__device__ __forceinline__ void fma2(u64& d, u64 a, u64 b) {
    asm("fma.rn.f32x2 %0, %1, %2, %0;" : "+l"(d) : "l"(a), "l"(b));
}

// inner step: 4 batch-splats x (2 h-pairs from w) -> 8 FFMA2
__device__ __forceinline__ void gemm_step(u64 accA[4], u64 accB[4],
                                          u64 a0, u64 a1, u64 a2, u64 a3,
                                          float4 w) {
    u64 wxy = pack2(w.x, w.y);
    u64 wzw = pack2(w.z, w.w);
    fma2(accA[0], a0, wxy); fma2(accB[0], a0, wzw);
    fma2(accA[1], a1, wxy); fma2(accB[1], a1, wzw);
    fma2(accA[2], a2, wxy); fma2(accB[2], a2, wzw);
    fma2(accA[3], a3, wxy); fma2(accB[3], a3, wzw);
}

// ---------------- prep: Wsum[mat][c][l] = W[c,l,0] + W[c,l,1]; zero sums ----
__global__ void k_wsum(const float* __restrict__ aw, const float* __restrict__ pw) {
    int idx = blockIdx.x * blockDim.x + threadIdx.x;
    if (idx < 8) ((double*)g_sumsA)[idx] = 0.0;
    if (idx >= 2 * C_ * 2 * H_ * H_) return;
    int mat = idx >> 15;
    int r   = idx & 32767;
    int c   = r >> 13;
    int l   = (r >> 12) & 1;
    int e   = r & 4095;
    const float* src = mat ? pw : aw;
    int base = ((c * 2 + l) * 2) * 4096;
    ((float*)g_Wsum)[idx] = src[base + e] + src[base + 4096 + e];
}

// ---------------- prep: compact nonzeros of the last diagonal block ---------
__global__ void k_compact(const float* __restrict__ adjf, const float* __restrict__ peaf) {
    int rowid = blockIdx.x;
    int mat = rowid / N_;
    int n   = rowid % N_;
    const float* A = mat ? peaf : adjf;
    int lane = threadIdx.x;
    int cnt = 0;
    for (int base = 0; base < N_; base += 32) {
        int m = base + lane;
        float w = (m < N_) ? A[(long)(OFF_ + n) * NB_ + OFF_ + m] : 0.f;
        unsigned mask = __ballot_sync(0xffffffffu, w != 0.f);
        if (w != 0.f) {
            int pos = cnt + __popc(mask & ((1u << lane) - 1u));
            g_cols[mat][n][pos] = m;
            g_vals[mat][n][pos] = w;
        }
        cnt += __popc(mask);
    }
    if (lane == 0) g_cnt[mat][n] = cnt;
}

// ---------------- per-checkpoint: gf / residual / h3 (x + norm inline) ------
__global__ void k_A(const float* __restrict__ inp, const float* __restrict__ w_in,
                    const float* __restrict__ b_in, const float* __restrict__ res_w,
                    const float* __restrict__ res_b, const float* __restrict__ gcw,
                    const float* __restrict__ gcb, int ck, int left) {
    __shared__ float s_mu, s_r;
    if (threadIdx.x == 0) {
        if (ck > 0) {
            double mu  = g_sumsA[ck - 1][0] / (double)BNH_;
            double var = g_sumsA[ck - 1][1] / (double)BNH_ - mu * mu;
            s_mu = (float)mu;
            s_r  = (float)rsqrt(var + 1e-5);
        } else { s_mu = 0.f; s_r = 0.f; }
    }
    __syncthreads();
    int idx = blockIdx.x * blockDim.x + threadIdx.x;
    if (idx >= BNH_) return;
    int h = idx & 63;
    int n = (idx >> 6) % N_;
    int b = idx / NH_;
    float w0 = w_in[h], w1 = w_in[64 + h], bi = b_in[h];
    float gf = 0.f, rs = 0.f, v = 0.f;
#pragma unroll
    for (int s = 0; s < 4; ++s) {
        if (ck > 0 && s == 0) {
            v = (g_cr[idx] - s_mu) * s_r;
        } else {
            int t = (ck == 0) ? s : (left + s - 1);
            const float2 ip = *(const float2*)(inp + (((long)b * T_ + t) * N_ + n) * 2);
            v = ip.x * w0 + ip.y * w1 + bi;
        }
        gf += gcw[s] * v;
        rs += res_w[s] * v;
    }
    g_gf[idx]  = gf + gcb[0];
    g_res[idx] = rs + res_b[0];
    g_h3[idx]  = v;
}

// ---------------- SpMM helper: gather 4 batch rows into duplicated smem -----
__device__ __forceinline__ void spmm4(const float* __restrict__ hsrc,
                                      const int* scols, const float* svals,
                                      int cnt, int b0, int hq,
                                      float2 (*sA2)[64], int brow) {
    const float4* h4 = (const float4*)hsrc + hq;
    float4 a0 = make_float4(0.f,0.f,0.f,0.f), a1 = a0, a2 = a0, a3 = a0;
    long r0 = (long)(b0 + 0) * (NH_ / 4);
    long r1 = r0 + (NH_ / 4), r2 = r1 + (NH_ / 4), r3 = r2 + (NH_ / 4);
    for (int i = 0; i < cnt; ++i) {
        int   mo = scols[i] * 16;
        float w  = svals[i];
        float4 v0 = h4[r0 + mo];
        float4 v1 = h4[r1 + mo];
        float4 v2 = h4[r2 + mo];
        float4 v3 = h4[r3 + mo];
        a0.x = fmaf(w, v0.x, a0.x); a0.y = fmaf(w, v0.y, a0.y);
        a0.z = fmaf(w, v0.z, a0.z); a0.w = fmaf(w, v0.w, a0.w);
        a1.x = fmaf(w, v1.x, a1.x); a1.y = fmaf(w, v1.y, a1.y);
        a1.z = fmaf(w, v1.z, a1.z); a1.w = fmaf(w, v1.w, a1.w);
        a2.x = fmaf(w, v2.x, a2.x); a2.y = fmaf(w, v2.y, a2.y);
        a2.z = fmaf(w, v2.z, a2.z); a2.w = fmaf(w, v2.w, a2.w);
        a3.x = fmaf(w, v3.x, a3.x); a3.y = fmaf(w, v3.y, a3.y);
        a3.z = fmaf(w, v3.z, a3.z); a3.w = fmaf(w, v3.w, a3.w);
    }
    int hc = hq * 4;
    sA2[brow + 0][hc + 0] = make_float2(a0.x, a0.x);
    sA2[brow + 0][hc + 1] = make_float2(a0.y, a0.y);
    sA2[brow + 0][hc + 2] = make_float2(a0.z, a0.z);
    sA2[brow + 0][hc + 3] = make_float2(a0.w, a0.w);
    sA2[brow + 1][hc + 0] = make_float2(a1.x, a1.x);
    sA2[brow + 1][hc + 1] = make_float2(a1.y, a1.y);
    sA2[brow + 1][hc + 2] = make_float2(a1.z, a1.z);
    sA2[brow + 1][hc + 3] = make_float2(a1.w, a1.w);
    sA2[brow + 2][hc + 0] = make_float2(a2.x, a2.x);
    sA2[brow + 2][hc + 1] = make_float2(a2.y, a2.y);
    sA2[brow + 2][hc + 2] = make_float2(a2.z, a2.z);
    sA2[brow + 2][hc + 3] = make_float2(a2.w, a2.w);
    sA2[brow + 3][hc + 0] = make_float2(a3.x, a3.x);
    sA2[brow + 3][hc + 1] = make_float2(a3.y, a3.y);
    sA2[brow + 3][hc + 2] = make_float2(a3.z, a3.z);
    sA2[brow + 3][hc + 3] = make_float2(a3.w, a3.w);
}

// ---------------- GCN layer 0: SpMM (32 batches) + 4x4 f32x2 GEMMs ----------
__global__ void __launch_bounds__(128) k_layer0(const float* __restrict__ gbA,
                                                const float* __restrict__ gbP) {
    __shared__ int    scols[336];
    __shared__ float  svals[336];
    __shared__ float2 sA2[32][64];
    int n   = blockIdx.x;
    int bg  = blockIdx.y;              // batch group of 32
    int mat = blockIdx.z;
    int t   = threadIdx.x;
    int cnt = g_cnt[mat][n];
    for (int i = t; i < cnt; i += 128) {
        scols[i] = g_cols[mat][n][i];
        svals[i] = g_vals[mat][n][i];
    }
    __syncthreads();

    int hq = t & 15, bq = t >> 4;      // bq 0..7
    spmm4(g_h3, scols, svals, cnt, bg * 32 + bq * 4, hq, sA2, bq * 4);
    __syncthreads();

    int tx = t & 15, ty = t >> 4;      // ty 0..7 -> 4 batches each
    const float* gb = mat ? gbP : gbA;
#pragma unroll
    for (int c = 0; c < C_; ++c) {
        const float4* W4 = (const float4*)g_Wsum[mat][c][0] + tx;
        float4 bias = ((const float4*)(gb + (c * 2) * 64))[tx];
        u64 bA = pack2(bias.x, bias.y), bB = pack2(bias.z, bias.w);
        u64 accA[4] = {bA, bA, bA, bA};
        u64 accB[4] = {bB, bB, bB, bB};
        const float2* A0 = sA2[ty * 4 + 0];
        const float2* A1 = sA2[ty * 4 + 1];
        const float2* A2 = sA2[ty * 4 + 2];
        const float2* A3 = sA2[ty * 4 + 3];
#pragma unroll 4
        for (int k = 0; k < 64; ++k) {
            gemm_step(accA, accB,
                      *(const u64*)&A0[k], *(const u64*)&A1[k],
                      *(const u64*)&A2[k], *(const u64*)&A3[k],
                      __ldg(&W4[k * 16]));
        }
        float* dst = g_H0[mat][c] + n * 64 + tx * 4;
#pragma unroll
        for (int j = 0; j < 4; ++j) {
            float2 lo = unpack2(accA[j]);
            float2 hi = unpack2(accB[j]);
            float4 o;
            o.x = lo.x > 0.f ? lo.x : 0.f;
            o.y = lo.y > 0.f ? lo.y : 0.f;
            o.z = hi.x > 0.f ? hi.x : 0.f;
            o.w = hi.y > 0.f ? hi.y : 0.f;
            *(float4*)(dst + (long)(bg * 32 + ty * 4 + j) * NH_) = o;
        }
    }
}

// ---------------- GCN layer 1: per-channel SpMM + f32x2 GEMM ----------------
__global__ void __launch_bounds__(128) k_layer1(const float* __restrict__ gbA,
                                                const float* __restrict__ gbP) {
    __shared__ int    scols[336];
    __shared__ float  svals[336];
    __shared__ float2 sA2[32][64];
    int n   = blockIdx.x;
    int bg  = blockIdx.y;
    int mat = blockIdx.z;
    int t   = threadIdx.x;
    int cnt = g_cnt[mat][n];
    for (int i = t; i < cnt; i += 128) {
        scols[i] = g_cols[mat][n][i];
        svals[i] = g_vals[mat][n][i];
    }
    __syncthreads();

    int hq = t & 15, bq = t >> 4;
    int tx = t & 15, ty = t >> 4;
    const float* gb = mat ? gbP : gbA;
#pragma unroll
    for (int c = 0; c < C_; ++c) {
        if (c) __syncthreads();
        spmm4(g_H0[mat][c], scols, svals, cnt, bg * 32 + bq * 4, hq, sA2, bq * 4);
        __syncthreads();
        const float4* W4 = (const float4*)g_Wsum[mat][c][1] + tx;
        float4 bias = ((const float4*)(gb + (c * 2 + 1) * 64))[tx];
        u64 bA = pack2(bias.x, bias.y), bB = pack2(bias.z, bias.w);
        u64 accA[4] = {bA, bA, bA, bA};
        u64 accB[4] = {bB, bB, bB, bB};
        const float2* A0 = sA2[ty * 4 + 0];
        const float2* A1 = sA2[ty * 4 + 1];
        const float2* A2 = sA2[ty * 4 + 2];
        const float2* A3 = sA2[ty * 4 + 3];
#pragma unroll 4
        for (int k = 0; k < 64; ++k) {
            gemm_step(accA, accB,
                      *(const u64*)&A0[k], *(const u64*)&A1[k],
                      *(const u64*)&A2[k], *(const u64*)&A3[k],
                      __ldg(&W4[k * 16]));
        }
        float* dst = g_C1[mat][c] + n * 64 + tx * 4;
#pragma unroll
        for (int j = 0; j < 4; ++j) {
            float2 lo = unpack2(accA[j]);
            float2 hi = unpack2(accB[j]);
            float4 o;
            o.x = lo.x > 0.f ? lo.x : 0.f;
            o.y = lo.y > 0.f ? lo.y : 0.f;
            o.z = hi.x > 0.f ? hi.x : 0.f;
            o.w = hi.y > 0.f ? hi.y : 0.f;
            *(float4*)(dst + (long)(bg * 32 + ty * 4 + j) * NH_) = o;
        }
    }
}

// ------- gate -> combine -> reduce -> +residual, fused LN partial sums ------
__global__ void __launch_bounds__(128) k_gate(
        const float* __restrict__ g1w, const float* __restrict__ g1b,
        const float* __restrict__ g2w, const float* __restrict__ g2b,
        const float* __restrict__ rw,  const float* __restrict__ rb, int ck) {
    __shared__ float2 sBuf[32][64];
    __shared__ float2 sG1[32][64];
    __shared__ double reds[4], redq[4];
    int t = threadIdx.x;
    long row0 = (long)blockIdx.x * 32;

    {   // load gf tile (duplicated pairs)
        const float* src = g_gf + row0 * 64;
#pragma unroll
        for (int i = 0; i < 16; ++i) {
            int idx = t + 128 * i;
            float v = src[idx];
            ((float2*)sBuf)[idx] = make_float2(v, v);
        }
    }
    __syncthreads();

    int tx = t & 15, ty = t >> 4;      // ty 0..7 -> rows ty*4..+3
    {   // stage 1: relu(gf @ g1w + g1b) -> sG1 (duplicated)
        const float4* W4 = (const float4*)g1w + tx;
        float4 b1 = ((const float4*)g1b)[tx];
        u64 bA = pack2(b1.x, b1.y), bB = pack2(b1.z, b1.w);
        u64 accA[4] = {bA, bA, bA, bA};
        u64 accB[4] = {bB, bB, bB, bB};
        const float2* A0 = sBuf[ty * 4 + 0];
        const float2* A1 = sBuf[ty * 4 + 1];
        const float2* A2 = sBuf[ty * 4 + 2];
        const float2* A3 = sBuf[ty * 4 + 3];
#pragma unroll 4
        for (int k = 0; k < 64; ++k) {
            gemm_step(accA, accB,
                      *(const u64*)&A0[k], *(const u64*)&A1[k],
                      *(const u64*)&A2[k], *(const u64*)&A3[k],
                      __ldg(&W4[k * 16]));
        }
#pragma unroll
        for (int j = 0; j < 4; ++j) {
            float2 lo = unpack2(accA[j]);
            float2 hi = unpack2(accB[j]);
            float r0 = lo.x > 0.f ? lo.x : 0.f;
            float r1 = lo.y > 0.f ? lo.y : 0.f;
            float r2 = hi.x > 0.f ? hi.x : 0.f;
            float r3 = hi.y > 0.f ? hi.y : 0.f;
            sG1[ty * 4 + j][tx * 4 + 0] = make_float2(r0, r0);
            sG1[ty * 4 + j][tx * 4 + 1] = make_float2(r1, r1);
            sG1[ty * 4 + j][tx * 4 + 2] = make_float2(r2, r2);
            sG1[ty * 4 + j][tx * 4 + 3] = make_float2(r3, r3);
        }
    }
    __syncthreads();

    float4 rbv = ((const float4*)rb)[tx];
    u64 r3A = pack2(rbv.x, rbv.y), r3B = pack2(rbv.z, rbv.w);
    u64 acc3A[4] = {r3A, r3A, r3A, r3A};
    u64 acc3B[4] = {r3B, r3B, r3B, r3B};
#pragma unroll
    for (int q = 0; q < 4; ++q) {
        // stage 2: sigmoid(sG1 @ g2w[:, q*64:+64] + b2), blend ca/cp
        float4 b2 = ((const float4*)(g2b + q * 64))[tx];
        u64 bA = pack2(b2.x, b2.y), bB = pack2(b2.z, b2.w);
        u64 acc2A[4] = {bA, bA, bA, bA};
        u64 acc2B[4] = {bB, bB, bB, bB};
        {
            const float4* W4 = (const float4*)(g2w + q * 64) + tx;
            const float2* A0 = sG1[ty * 4 + 0];
            const float2* A1 = sG1[ty * 4 + 1];
            const float2* A2 = sG1[ty * 4 + 2];
            const float2* A3 = sG1[ty * 4 + 3];
#pragma unroll 4
            for (int k = 0; k < 64; ++k) {
                gemm_step(acc2A, acc2B,
                          *(const u64*)&A0[k], *(const u64*)&A1[k],
                          *(const u64*)&A2[k], *(const u64*)&A3[k],
                          __ldg(&W4[k * 64]));
            }
        }
        __syncthreads();               // protect sBuf (prev stage-3 / gf reads)
#pragma unroll
        for (int j = 0; j < 4; ++j) {
            long rr = (row0 + ty * 4 + j) * 64 + tx * 4;
            float4 ca = *(const float4*)&g_C1[0][q][rr];
            float4 cp = *(const float4*)&g_C1[1][q][rr];
            float2 lo = unpack2(acc2A[j]);
            float2 hi = unpack2(acc2B[j]);
            float g0 = 1.f / (1.f + expf(-lo.x));
            float g1 = 1.f / (1.f + expf(-lo.y));
            float g2 = 1.f / (1.f + expf(-hi.x));
            float g3 = 1.f / (1.f + expf(-hi.y));
            float o0 = g0 * ca.x + (1.f - g0) * cp.x;
            float o1 = g1 * ca.y + (1.f - g1) * cp.y;
            float o2 = g2 * ca.z + (1.f - g2) * cp.z;
            float o3 = g3 * ca.w + (1.f - g3) * cp.w;
            sBuf[ty * 4 + j][tx * 4 + 0] = make_float2(o0, o0);
            sBuf[ty * 4 + j][tx * 4 + 1] = make_float2(o1, o1);
            sBuf[ty * 4 + j][tx * 4 + 2] = make_float2(o2, o2);
            sBuf[ty * 4 + j][tx * 4 + 3] = make_float2(o3, o3);
        }
        __syncthreads();
        // stage 3 partial: acc3 += sBuf @ rw[q*64:+64, :]
        {
            const float4* W4 = (const float4*)(rw + (q * 64) * 64) + tx;
            const float2* A0 = sBuf[ty * 4 + 0];
            const float2* A1 = sBuf[ty * 4 + 1];
            const float2* A2 = sBuf[ty * 4 + 2];
            const float2* A3 = sBuf[ty * 4 + 3];
#pragma unroll 4
            for (int k = 0; k < 64; ++k) {
                gemm_step(acc3A, acc3B,
                          *(const u64*)&A0[k], *(const u64*)&A1[k],
                          *(const u64*)&A2[k], *(const u64*)&A3[k],
                          __ldg(&W4[k * 16]));
            }
        }
    }

    // epilogue: + residual, store cr, LN partial sums
    double ls = 0.0, lq = 0.0;
#pragma unroll
    for (int j = 0; j < 4; ++j) {
        long rr = (row0 + ty * 4 + j) * 64 + tx * 4;
        float4 rv = *(const float4*)&g_res[rr];
        float2 lo = unpack2(acc3A[j]);
        float2 hi = unpack2(acc3B[j]);
        float4 v;
        v.x = lo.x + rv.x; v.y = lo.y + rv.y;
        v.z = hi.x + rv.z; v.w = hi.y + rv.w;
        *(float4*)&g_cr[rr] = v;
        ls += (double)v.x + (double)v.y + (double)v.z + (double)v.w;
        lq += (double)v.x * v.x + (double)v.y * v.y +
              (double)v.z * v.z + (double)v.w * v.w;
    }
    for (int off = 16; off > 0; off >>= 1) {
        ls += __shfl_down_sync(0xffffffffu, ls, off);
        lq += __shfl_down_sync(0xffffffffu, lq, off);
    }
    int wid = t >> 5;
    if ((t & 31) == 0) { reds[wid] = ls; redq[wid] = lq; }
    __syncthreads();
    if (wid == 0) {
        ls = (t < 4) ? reds[t] : 0.0;
        lq = (t < 4) ? redq[t] : 0.0;
        for (int off = 2; off > 0; off >>= 1) {
            ls += __shfl_down_sync(0xffffffffu, ls, off);
            lq += __shfl_down_sync(0xffffffffu, lq, off);
        }
        if (t == 0) {
            atomicAdd(&g_sumsA[ck][0], ls);
            atomicAdd(&g_sumsA[ck][1], lq);
        }
    }
}

// ---------------- final: norm inline, 1x1 conv over P + linear H->1 ---------
__global__ void k_out(const float* __restrict__ cw, const float* __restrict__ cb,
                      const float* __restrict__ lw, const float* __restrict__ lb,
                      float* __restrict__ out) {
    __shared__ float red[4][2];
    __shared__ float s_mu, s_r;
    int t = threadIdx.x;
    if (t == 0) {
        double mu  = g_sumsA[3][0] / (double)BNH_;
        double var = g_sumsA[3][1] / (double)BNH_ - mu * mu;
        s_mu = (float)mu;
        s_r  = (float)rsqrt(var + 1e-5);
    }
    __syncthreads();
    int h  = t & 63;
    int rl = t >> 6;
    int row = blockIdx.x * 4 + rl;
    int b = row / N_, n = row % N_;
    float v   = (g_cr[(long)row * 64 + h] - s_mu) * s_r;
    float lin = lw[h];
    int lane = t & 31;
    int w2   = (t >> 5) & 1;
    for (int p = 0; p < P_; ++p) {
        float x = cw[p] * v + cb[p];
        x = x > 0.f ? x : 0.f;
        float s = x * lin;
#pragma unroll
        for (int o = 16; o > 0; o >>= 1) s += __shfl_down_sync(0xffffffffu, s, o);
        if (lane == 0) red[rl][w2] = s;
        __syncthreads();
        if (h == 0) out[((long)b * P_ + p) * N_ + n] = red[rl][0] + red[rl][1] + lb[0];
        __syncthreads();
    }
}

// ---------------- launcher ---------------------------------------------------
extern "C" void kernel_launch(void* const* d_in, const int* in_sizes, int n_in,
                              void* d_out, int out_size) {
    const float* inputs    = (const float*)d_in[0];
    const float* adj_fwd   = (const float*)d_in[1];
    const float* pea_fwd   = (const float*)d_in[3];
    const float* w_in      = (const float*)d_in[5];
    const float* b_in      = (const float*)d_in[6];
    const float* res_w     = (const float*)d_in[7];
    const float* res_b     = (const float*)d_in[8];
    const float* gconv_w   = (const float*)d_in[9];
    const float* gconv_b   = (const float*)d_in[10];
    const float* gate1_w   = (const float*)d_in[11];
    const float* gate1_b   = (const float*)d_in[12];
    const float* gate2_w   = (const float*)d_in[13];
    const float* gate2_b   = (const float*)d_in[14];
    const float* reduce_w  = (const float*)d_in[15];
    const float* reduce_b  = (const float*)d_in[16];
    const float* gcn_adj_w = (const float*)d_in[17];
    const float* gcn_adj_b = (const float*)d_in[18];
    const float* gcn_pea_w = (const float*)d_in[19];
    const float* gcn_pea_b = (const float*)d_in[20];
    const float* out_cw    = (const float*)d_in[21];
    const float* out_cb    = (const float*)d_in[22];
    const float* out_lw    = (const float*)d_in[23];
    const float* out_lb    = (const float*)d_in[24];
    float* out = (float*)d_out;

    k_wsum<<<256, 256>>>(gcn_adj_w, gcn_pea_w);
    k_compact<<<2 * N_, 32>>>(adj_fwd, pea_fwd);

    const int lefts[4] = {0, 4, 7, 10};
    dim3 gl(N_, 2, 2);                 // (n, batch-group, mat) = 1300 blocks
    for (int ck = 0; ck < 4; ++ck) {
        k_A<<<BNH_ / 256, 256>>>(inputs, w_in, b_in, res_w, res_b,
                                 gconv_w, gconv_b, ck, lefts[ck]);
        k_layer0<<<gl, 128>>>(gcn_adj_b, gcn_pea_b);
        k_layer1<<<gl, 128>>>(gcn_adj_b, gcn_pea_b);
        k_gate<<<BNH_ / 64 / 32, 128>>>(gate1_w, gate1_b, gate2_w, gate2_b,
                                        reduce_w, reduce_b, ck);
    }
    k_out<<<(B_ * N_) / 4, 256>>>(out_cw, out_cb, out_lw, out_lb, out);
}

// round 7
// speedup vs baseline: 1.4609x; 1.1168x over previous
#include <cuda_runtime.h>

#define B_   64
#define T_   13
#define N_   325
#define H_   64
#define C_   4
#define S_   4
#define P_   12
#define NB_  1300
#define OFF_ 975
#define NH_  (N_*H_)        // 20800
#define BNH_ (B_*NH_)       // 1331200

typedef unsigned long long u64;

// ---------------- scratch (device globals; no runtime alloc allowed) --------
__device__ float  g_gf  [BNH_];
__device__ float  g_res [BNH_];
__device__ float  g_h3  [BNH_];
__device__ float  g_cr  [BNH_];
__device__ float  g_H0  [2][C_][BNH_];
__device__ float  g_C1  [2][C_][BNH_];
__device__ float  g_Wsum[2][C_][2][H_*H_];
__device__ int    g_cols[2][N_][N_];
__device__ float  g_vals[2][N_][N_];
__device__ int    g_cnt [2][N_];
__device__ double g_sumsA[4][2];         // per-checkpoint (sum, sumsq)

// ---------------- f32x2 packed helpers (used by k_gate) ---------------------
__device__ __forceinline__ u64 pack2(float x, float y) {
    u64 r;
    asm("mov.b64 %0, {%1, %2};" : "=l"(r) : "f"(x), "f"(y));
    return r;
}
__device__ __forceinline__ float2 unpack2(u64 v) {
    float2 r;
    asm("mov.b64 {%0, %1}, %2;" : "=f"(r.x), "=f"(r.y) : "l"(v));
    return r;
}
__device__ __forceinline__ void fma2(u64& d, u64 a, u64 b) {
    asm("fma.rn.f32x2 %0, %1, %2, %0;" : "+l"(d) : "l"(a), "l"(b));
}
__device__ __forceinline__ void gemm_step(u64 accA[4], u64 accB[4],
                                          u64 a0, u64 a1, u64 a2, u64 a3,
                                          float4 w) {
    u64 wxy = pack2(w.x, w.y);
    u64 wzw = pack2(w.z, w.w);
    fma2(accA[0], a0, wxy); fma2(accB[0], a0, wzw);
    fma2(accA[1], a1, wxy); fma2(accB[1], a1, wzw);
    fma2(accA[2], a2, wxy); fma2(accB[2], a2, wzw);
    fma2(accA[3], a3, wxy); fma2(accB[3], a3, wzw);
}

// ---------------- scalar 4x4 helpers -----------------------------------------
__device__ __forceinline__ void fma16(float4 acc[4], float a0, float a1, float a2,
                                      float a3, float4 w) {
    acc[0].x = fmaf(a0, w.x, acc[0].x); acc[0].y = fmaf(a0, w.y, acc[0].y);
    acc[0].z = fmaf(a0, w.z, acc[0].z); acc[0].w = fmaf(a0, w.w, acc[0].w);
    acc[1].x = fmaf(a1, w.x, acc[1].x); acc[1].y = fmaf(a1, w.y, acc[1].y);
    acc[1].z = fmaf(a1, w.z, acc[1].z); acc[1].w = fmaf(a1, w.w, acc[1].w);
    acc[2].x = fmaf(a2, w.x, acc[2].x); acc[2].y = fmaf(a2, w.y, acc[2].y);
    acc[2].z = fmaf(a2, w.z, acc[2].z); acc[2].w = fmaf(a2, w.w, acc[2].w);
    acc[3].x = fmaf(a3, w.x, acc[3].x); acc[3].y = fmaf(a3, w.y, acc[3].y);
    acc[3].z = fmaf(a3, w.z, acc[3].z); acc[3].w = fmaf(a3, w.w, acc[3].w);
}
__device__ __forceinline__ float4 relu4(float4 v) {
    v.x = v.x > 0.f ? v.x : 0.f; v.y = v.y > 0.f ? v.y : 0.f;
    v.z = v.z > 0.f ? v.z : 0.f; v.w = v.w > 0.f ? v.w : 0.f;
    return v;
}
__device__ __forceinline__ void fma4v(float4& a, float w, float4 v) {
    a.x = fmaf(w, v.x, a.x); a.y = fmaf(w, v.y, a.y);
    a.z = fmaf(w, v.z, a.z); a.w = fmaf(w, v.w, a.w);
}

// ---------------- prep: Wsum[mat][c][l] = W[c,l,0] + W[c,l,1]; zero sums ----
__global__ void k_wsum(const float* __restrict__ aw, const float* __restrict__ pw) {
    int idx = blockIdx.x * blockDim.x + threadIdx.x;
    if (idx < 8) ((double*)g_sumsA)[idx] = 0.0;
    if (idx >= 2 * C_ * 2 * H_ * H_) return;
    int mat = idx >> 15;
    int r   = idx & 32767;
    int c   = r >> 13;
    int l   = (r >> 12) & 1;
    int e   = r & 4095;
    const float* src = mat ? pw : aw;
    int base = ((c * 2 + l) * 2) * 4096;
    ((float*)g_Wsum)[idx] = src[base + e] + src[base + 4096 + e];
}

// ---------------- prep: compact nonzeros of the last diagonal block ---------
__global__ void k_compact(const float* __restrict__ adjf, const float* __restrict__ peaf) {
    int rowid = blockIdx.x;
    int mat = rowid / N_;
    int n   = rowid % N_;
    const float* A = mat ? peaf : adjf;
    int lane = threadIdx.x;
    int cnt = 0;
    for (int base = 0; base < N_; base += 32) {
        int m = base + lane;
        float w = (m < N_) ? A[(long)(OFF_ + n) * NB_ + OFF_ + m] : 0.f;
        unsigned mask = __ballot_sync(0xffffffffu, w != 0.f);
        if (w != 0.f) {
            int pos = cnt + __popc(mask & ((1u << lane) - 1u));
            g_cols[mat][n][pos] = m;
            g_vals[mat][n][pos] = w;
        }
        cnt += __popc(mask);
    }
    if (lane == 0) g_cnt[mat][n] = cnt;
}

// ---------------- per-checkpoint: gf / residual / h3 (x + norm inline) ------
__global__ void k_A(const float* __restrict__ inp, const float* __restrict__ w_in,
                    const float* __restrict__ b_in, const float* __restrict__ res_w,
                    const float* __restrict__ res_b, const float* __restrict__ gcw,
                    const float* __restrict__ gcb, int ck, int left) {
    __shared__ float s_mu, s_r;
    if (threadIdx.x == 0) {
        if (ck > 0) {
            double mu  = g_sumsA[ck - 1][0] / (double)BNH_;
            double var = g_sumsA[ck - 1][1] / (double)BNH_ - mu * mu;
            s_mu = (float)mu;
            s_r  = (float)rsqrt(var + 1e-5);
        } else { s_mu = 0.f; s_r = 0.f; }
    }
    __syncthreads();
    int idx = blockIdx.x * blockDim.x + threadIdx.x;
    if (idx >= BNH_) return;
    int h = idx & 63;
    int n = (idx >> 6) % N_;
    int b = idx / NH_;
    float w0 = w_in[h], w1 = w_in[64 + h], bi = b_in[h];
    float gf = 0.f, rs = 0.f, v = 0.f;
#pragma unroll
    for (int s = 0; s < 4; ++s) {
        if (ck > 0 && s == 0) {
            v = (g_cr[idx] - s_mu) * s_r;
        } else {
            int t = (ck == 0) ? s : (left + s - 1);
            const float2 ip = *(const float2*)(inp + (((long)b * T_ + t) * N_ + n) * 2);
            v = ip.x * w0 + ip.y * w1 + bi;
        }
        gf += gcw[s] * v;
        rs += res_w[s] * v;
    }
    g_gf[idx]  = gf + gcb[0];
    g_res[idx] = rs + res_b[0];
    g_h3[idx]  = v;
}

// ---------------- GCN layer 0: SpMM (16 batches, MLP8) + 4x4 GEMMs ----------
// grid (N_, 4, 2); block 64
__global__ void __launch_bounds__(64) k_layer0(const float* __restrict__ gbA,
                                               const float* __restrict__ gbP) {
    __shared__ int   scols[336];
    __shared__ float svals[336];
    __shared__ float sA[16][64];
    int n   = blockIdx.x;
    int bg  = blockIdx.y;
    int mat = blockIdx.z;
    int t   = threadIdx.x;
    int cnt = g_cnt[mat][n];
    for (int i = t; i < cnt; i += 64) {
        scols[i] = g_cols[mat][n][i];
        svals[i] = g_vals[mat][n][i];
    }
    __syncthreads();

    int hq = t & 15, bq = t >> 4;          // bq 0..3
    int b0 = bg * 16 + bq * 4;
    {
        const float4* h4 = (const float4*)g_h3 + hq;
        long r0 = (long)b0 * (NH_ / 4);
        long r1 = r0 + (NH_ / 4), r2 = r1 + (NH_ / 4), r3 = r2 + (NH_ / 4);
        float4 a0 = make_float4(0.f,0.f,0.f,0.f), a1 = a0, a2 = a0, a3 = a0;
        float4 b0v = a0, b1v = a0, b2v = a0, b3v = a0;
        int i = 0;
        for (; i + 2 <= cnt; i += 2) {
            int   moA = scols[i] * 16,  moB = scols[i + 1] * 16;
            float wA  = svals[i],       wB  = svals[i + 1];
            float4 vA0 = h4[r0 + moA], vB0 = h4[r0 + moB];
            float4 vA1 = h4[r1 + moA], vB1 = h4[r1 + moB];
            float4 vA2 = h4[r2 + moA], vB2 = h4[r2 + moB];
            float4 vA3 = h4[r3 + moA], vB3 = h4[r3 + moB];
            fma4v(a0, wA, vA0); fma4v(b0v, wB, vB0);
            fma4v(a1, wA, vA1); fma4v(b1v, wB, vB1);
            fma4v(a2, wA, vA2); fma4v(b2v, wB, vB2);
            fma4v(a3, wA, vA3); fma4v(b3v, wB, vB3);
        }
        if (i < cnt) {
            int   mo = scols[i] * 16;
            float w  = svals[i];
            fma4v(a0, w, h4[r0 + mo]);
            fma4v(a1, w, h4[r1 + mo]);
            fma4v(a2, w, h4[r2 + mo]);
            fma4v(a3, w, h4[r3 + mo]);
        }
        a0.x += b0v.x; a0.y += b0v.y; a0.z += b0v.z; a0.w += b0v.w;
        a1.x += b1v.x; a1.y += b1v.y; a1.z += b1v.z; a1.w += b1v.w;
        a2.x += b2v.x; a2.y += b2v.y; a2.z += b2v.z; a2.w += b2v.w;
        a3.x += b3v.x; a3.y += b3v.y; a3.z += b3v.z; a3.w += b3v.w;
        *(float4*)&sA[bq * 4 + 0][hq * 4] = a0;
        *(float4*)&sA[bq * 4 + 1][hq * 4] = a1;
        *(float4*)&sA[bq * 4 + 2][hq * 4] = a2;
        *(float4*)&sA[bq * 4 + 3][hq * 4] = a3;
    }
    __syncthreads();

    int tx = t & 15, ty = t >> 4;          // ty 0..3
    const float* gb = mat ? gbP : gbA;
#pragma unroll
    for (int c = 0; c < C_; ++c) {
        const float4* W4 = (const float4*)g_Wsum[mat][c][0] + tx;
        float4 bias = ((const float4*)(gb + (c * 2) * 64))[tx];
        float4 acc[4] = {bias, bias, bias, bias};
        const float* A0 = sA[ty * 4 + 0];
        const float* A1 = sA[ty * 4 + 1];
        const float* A2 = sA[ty * 4 + 2];
        const float* A3 = sA[ty * 4 + 3];
#pragma unroll 4
        for (int k = 0; k < 64; ++k)
            fma16(acc, A0[k], A1[k], A2[k], A3[k], __ldg(&W4[k * 16]));
        float* dst = g_H0[mat][c] + n * 64 + tx * 4;
#pragma unroll
        for (int j = 0; j < 4; ++j)
            *(float4*)(dst + (long)(bg * 16 + ty * 4 + j) * NH_) = relu4(acc[j]);
    }
}

// ---------------- GCN layer 1: 2-channel-paired SpMM (MLP8) + GEMMs ---------
// grid (N_, 4, 2); block 64
__global__ void __launch_bounds__(64) k_layer1(const float* __restrict__ gbA,
                                               const float* __restrict__ gbP) {
    __shared__ int   scols[336];
    __shared__ float svals[336];
    __shared__ float sA[2][16][64];
    int n   = blockIdx.x;
    int bg  = blockIdx.y;
    int mat = blockIdx.z;
    int t   = threadIdx.x;
    int cnt = g_cnt[mat][n];
    for (int i = t; i < cnt; i += 64) {
        scols[i] = g_cols[mat][n][i];
        svals[i] = g_vals[mat][n][i];
    }
    __syncthreads();

    int hq = t & 15, bq = t >> 4;
    int tx = t & 15, ty = t >> 4;
    int b0 = bg * 16 + bq * 4;
    long r0 = (long)b0 * (NH_ / 4);
    long r1 = r0 + (NH_ / 4), r2 = r1 + (NH_ / 4), r3 = r2 + (NH_ / 4);
    const float* gb = mat ? gbP : gbA;

#pragma unroll
    for (int pass = 0; pass < 2; ++pass) {
        if (pass) __syncthreads();
        int c0 = pass * 2;
        {   // SpMM for channels c0, c0+1 simultaneously: 8 loads in flight
            const float4* hA = (const float4*)g_H0[mat][c0]     + hq;
            const float4* hB = (const float4*)g_H0[mat][c0 + 1] + hq;
            float4 aA0 = make_float4(0.f,0.f,0.f,0.f), aA1 = aA0, aA2 = aA0, aA3 = aA0;
            float4 aB0 = aA0, aB1 = aA0, aB2 = aA0, aB3 = aA0;
            for (int i = 0; i < cnt; ++i) {
                int   mo = scols[i] * 16;
                float w  = svals[i];
                float4 vA0 = hA[r0 + mo];
                float4 vA1 = hA[r1 + mo];
                float4 vA2 = hA[r2 + mo];
                float4 vA3 = hA[r3 + mo];
                float4 vB0 = hB[r0 + mo];
                float4 vB1 = hB[r1 + mo];
                float4 vB2 = hB[r2 + mo];
                float4 vB3 = hB[r3 + mo];
                fma4v(aA0, w, vA0); fma4v(aA1, w, vA1);
                fma4v(aA2, w, vA2); fma4v(aA3, w, vA3);
                fma4v(aB0, w, vB0); fma4v(aB1, w, vB1);
                fma4v(aB2, w, vB2); fma4v(aB3, w, vB3);
            }
            *(float4*)&sA[0][bq * 4 + 0][hq * 4] = aA0;
            *(float4*)&sA[0][bq * 4 + 1][hq * 4] = aA1;
            *(float4*)&sA[0][bq * 4 + 2][hq * 4] = aA2;
            *(float4*)&sA[0][bq * 4 + 3][hq * 4] = aA3;
            *(float4*)&sA[1][bq * 4 + 0][hq * 4] = aB0;
            *(float4*)&sA[1][bq * 4 + 1][hq * 4] = aB1;
            *(float4*)&sA[1][bq * 4 + 2][hq * 4] = aB2;
            *(float4*)&sA[1][bq * 4 + 3][hq * 4] = aB3;
        }
        __syncthreads();
#pragma unroll
        for (int cc = 0; cc < 2; ++cc) {
            int c = c0 + cc;
            const float4* W4 = (const float4*)g_Wsum[mat][c][1] + tx;
            float4 bias = ((const float4*)(gb + (c * 2 + 1) * 64))[tx];
            float4 acc[4] = {bias, bias, bias, bias};
            const float* A0 = sA[cc][ty * 4 + 0];
            const float* A1 = sA[cc][ty * 4 + 1];
            const float* A2 = sA[cc][ty * 4 + 2];
            const float* A3 = sA[cc][ty * 4 + 3];
#pragma unroll 4
            for (int k = 0; k < 64; ++k)
                fma16(acc, A0[k], A1[k], A2[k], A3[k], __ldg(&W4[k * 16]));
            float* dst = g_C1[mat][c] + n * 64 + tx * 4;
#pragma unroll
            for (int j = 0; j < 4; ++j)
                *(float4*)(dst + (long)(bg * 16 + ty * 4 + j) * NH_) = relu4(acc[j]);
        }
    }
}

// ------- gate -> combine -> reduce -> +residual, fused LN partial sums ------
__global__ void __launch_bounds__(128) k_gate(
        const float* __restrict__ g1w, const float* __restrict__ g1b,
        const float* __restrict__ g2w, const float* __restrict__ g2b,
        const float* __restrict__ rw,  const float* __restrict__ rb, int ck) {
    __shared__ float2 sBuf[32][64];
    __shared__ float2 sG1[32][64];
    __shared__ double reds[4], redq[4];
    int t = threadIdx.x;
    long row0 = (long)blockIdx.x * 32;

    {   // load gf tile (duplicated pairs)
        const float* src = g_gf + row0 * 64;
#pragma unroll
        for (int i = 0; i < 16; ++i) {
            int idx = t + 128 * i;
            float v = src[idx];
            ((float2*)sBuf)[idx] = make_float2(v, v);
        }
    }
    __syncthreads();

    int tx = t & 15, ty = t >> 4;
    {   // stage 1: relu(gf @ g1w + g1b) -> sG1 (duplicated)
        const float4* W4 = (const float4*)g1w + tx;
        float4 b1 = ((const float4*)g1b)[tx];
        u64 bA = pack2(b1.x, b1.y), bB = pack2(b1.z, b1.w);
        u64 accA[4] = {bA, bA, bA, bA};
        u64 accB[4] = {bB, bB, bB, bB};
        const float2* A0 = sBuf[ty * 4 + 0];
        const float2* A1 = sBuf[ty * 4 + 1];
        const float2* A2 = sBuf[ty * 4 + 2];
        const float2* A3 = sBuf[ty * 4 + 3];
#pragma unroll 4
        for (int k = 0; k < 64; ++k) {
            gemm_step(accA, accB,
                      *(const u64*)&A0[k], *(const u64*)&A1[k],
                      *(const u64*)&A2[k], *(const u64*)&A3[k],
                      __ldg(&W4[k * 16]));
        }
#pragma unroll
        for (int j = 0; j < 4; ++j) {
            float2 lo = unpack2(accA[j]);
            float2 hi = unpack2(accB[j]);
            float r0 = lo.x > 0.f ? lo.x : 0.f;
            float r1 = lo.y > 0.f ? lo.y : 0.f;
            float r2 = hi.x > 0.f ? hi.x : 0.f;
            float r3 = hi.y > 0.f ? hi.y : 0.f;
            sG1[ty * 4 + j][tx * 4 + 0] = make_float2(r0, r0);
            sG1[ty * 4 + j][tx * 4 + 1] = make_float2(r1, r1);
            sG1[ty * 4 + j][tx * 4 + 2] = make_float2(r2, r2);
            sG1[ty * 4 + j][tx * 4 + 3] = make_float2(r3, r3);
        }
    }
    __syncthreads();

    float4 rbv = ((const float4*)rb)[tx];
    u64 r3A = pack2(rbv.x, rbv.y), r3B = pack2(rbv.z, rbv.w);
    u64 acc3A[4] = {r3A, r3A, r3A, r3A};
    u64 acc3B[4] = {r3B, r3B, r3B, r3B};
#pragma unroll
    for (int q = 0; q < 4; ++q) {
        float4 b2 = ((const float4*)(g2b + q * 64))[tx];
        u64 bA = pack2(b2.x, b2.y), bB = pack2(b2.z, b2.w);
        u64 acc2A[4] = {bA, bA, bA, bA};
        u64 acc2B[4] = {bB, bB, bB, bB};
        {
            const float4* W4 = (const float4*)(g2w + q * 64) + tx;
            const float2* A0 = sG1[ty * 4 + 0];
            const float2* A1 = sG1[ty * 4 + 1];
            const float2* A2 = sG1[ty * 4 + 2];
            const float2* A3 = sG1[ty * 4 + 3];
#pragma unroll 4
            for (int k = 0; k < 64; ++k) {
                gemm_step(acc2A, acc2B,
                          *(const u64*)&A0[k], *(const u64*)&A1[k],
                          *(const u64*)&A2[k], *(const u64*)&A3[k],
                          __ldg(&W4[k * 64]));
            }
        }
        __syncthreads();
#pragma unroll
        for (int j = 0; j < 4; ++j) {
            long rr = (row0 + ty * 4 + j) * 64 + tx * 4;
            float4 ca = *(const float4*)&g_C1[0][q][rr];
            float4 cp = *(const float4*)&g_C1[1][q][rr];
            float2 lo = unpack2(acc2A[j]);
            float2 hi = unpack2(acc2B[j]);
            float g0 = 1.f / (1.f + expf(-lo.x));
            float g1 = 1.f / (1.f + expf(-lo.y));
            float g2 = 1.f / (1.f + expf(-hi.x));
            float g3 = 1.f / (1.f + expf(-hi.y));
            float o0 = g0 * ca.x + (1.f - g0) * cp.x;
            float o1 = g1 * ca.y + (1.f - g1) * cp.y;
            float o2 = g2 * ca.z + (1.f - g2) * cp.z;
            float o3 = g3 * ca.w + (1.f - g3) * cp.w;
            sBuf[ty * 4 + j][tx * 4 + 0] = make_float2(o0, o0);
            sBuf[ty * 4 + j][tx * 4 + 1] = make_float2(o1, o1);
            sBuf[ty * 4 + j][tx * 4 + 2] = make_float2(o2, o2);
            sBuf[ty * 4 + j][tx * 4 + 3] = make_float2(o3, o3);
        }
        __syncthreads();
        {
            const float4* W4 = (const float4*)(rw + (q * 64) * 64) + tx;
            const float2* A0 = sBuf[ty * 4 + 0];
            const float2* A1 = sBuf[ty * 4 + 1];
            const float2* A2 = sBuf[ty * 4 + 2];
            const float2* A3 = sBuf[ty * 4 + 3];
#pragma unroll 4
            for (int k = 0; k < 64; ++k) {
                gemm_step(acc3A, acc3B,
                          *(const u64*)&A0[k], *(const u64*)&A1[k],
                          *(const u64*)&A2[k], *(const u64*)&A3[k],
                          __ldg(&W4[k * 16]));
            }
        }
    }

    double ls = 0.0, lq = 0.0;
#pragma unroll
    for (int j = 0; j < 4; ++j) {
        long rr = (row0 + ty * 4 + j) * 64 + tx * 4;
        float4 rv = *(const float4*)&g_res[rr];
        float2 lo = unpack2(acc3A[j]);
        float2 hi = unpack2(acc3B[j]);
        float4 v;
        v.x = lo.x + rv.x; v.y = lo.y + rv.y;
        v.z = hi.x + rv.z; v.w = hi.y + rv.w;
        *(float4*)&g_cr[rr] = v;
        ls += (double)v.x + (double)v.y + (double)v.z + (double)v.w;
        lq += (double)v.x * v.x + (double)v.y * v.y +
              (double)v.z * v.z + (double)v.w * v.w;
    }
    for (int off = 16; off > 0; off >>= 1) {
        ls += __shfl_down_sync(0xffffffffu, ls, off);
        lq += __shfl_down_sync(0xffffffffu, lq, off);
    }
    int wid = t >> 5;
    if ((t & 31) == 0) { reds[wid] = ls; redq[wid] = lq; }
    __syncthreads();
    if (wid == 0) {
        ls = (t < 4) ? reds[t] : 0.0;
        lq = (t < 4) ? redq[t] : 0.0;
        for (int off = 2; off > 0; off >>= 1) {
            ls += __shfl_down_sync(0xffffffffu, ls, off);
            lq += __shfl_down_sync(0xffffffffu, lq, off);
        }
        if (t == 0) {
            atomicAdd(&g_sumsA[ck][0], ls);
            atomicAdd(&g_sumsA[ck][1], lq);
        }
    }
}

// ---------------- final: norm inline, 1x1 conv over P + linear H->1 ---------
__global__ void k_out(const float* __restrict__ cw, const float* __restrict__ cb,
                      const float* __restrict__ lw, const float* __restrict__ lb,
                      float* __restrict__ out) {
    __shared__ float red[4][2];
    __shared__ float s_mu, s_r;
    int t = threadIdx.x;
    if (t == 0) {
        double mu  = g_sumsA[3][0] / (double)BNH_;
        double var = g_sumsA[3][1] / (double)BNH_ - mu * mu;
        s_mu = (float)mu;
        s_r  = (float)rsqrt(var + 1e-5);
    }
    __syncthreads();
    int h  = t & 63;
    int rl = t >> 6;
    int row = blockIdx.x * 4 + rl;
    int b = row / N_, n = row % N_;
    float v   = (g_cr[(long)row * 64 + h] - s_mu) * s_r;
    float lin = lw[h];
    int lane = t & 31;
    int w2   = (t >> 5) & 1;
    for (int p = 0; p < P_; ++p) {
        float x = cw[p] * v + cb[p];
        x = x > 0.f ? x : 0.f;
        float s = x * lin;
#pragma unroll
        for (int o = 16; o > 0; o >>= 1) s += __shfl_down_sync(0xffffffffu, s, o);
        if (lane == 0) red[rl][w2] = s;
        __syncthreads();
        if (h == 0) out[((long)b * P_ + p) * N_ + n] = red[rl][0] + red[rl][1] + lb[0];
        __syncthreads();
    }
}

// ---------------- launcher ---------------------------------------------------
extern "C" void kernel_launch(void* const* d_in, const int* in_sizes, int n_in,
                              void* d_out, int out_size) {
    const float* inputs    = (const float*)d_in[0];
    const float* adj_fwd   = (const float*)d_in[1];
    const float* pea_fwd   = (const float*)d_in[3];
    const float* w_in      = (const float*)d_in[5];
    const float* b_in      = (const float*)d_in[6];
    const float* res_w     = (const float*)d_in[7];
    const float* res_b     = (const float*)d_in[8];
    const float* gconv_w   = (const float*)d_in[9];
    const float* gconv_b   = (const float*)d_in[10];
    const float* gate1_w   = (const float*)d_in[11];
    const float* gate1_b   = (const float*)d_in[12];
    const float* gate2_w   = (const float*)d_in[13];
    const float* gate2_b   = (const float*)d_in[14];
    const float* reduce_w  = (const float*)d_in[15];
    const float* reduce_b  = (const float*)d_in[16];
    const float* gcn_adj_w = (const float*)d_in[17];
    const float* gcn_adj_b = (const float*)d_in[18];
    const float* gcn_pea_w = (const float*)d_in[19];
    const float* gcn_pea_b = (const float*)d_in[20];
    const float* out_cw    = (const float*)d_in[21];
    const float* out_cb    = (const float*)d_in[22];
    const float* out_lw    = (const float*)d_in[23];
    const float* out_lb    = (const float*)d_in[24];
    float* out = (float*)d_out;

    k_wsum<<<256, 256>>>(gcn_adj_w, gcn_pea_w);
    k_compact<<<2 * N_, 32>>>(adj_fwd, pea_fwd);

    const int lefts[4] = {0, 4, 7, 10};
    dim3 gl(N_, 4, 2);                 // (n, batch-group of 16, mat)
    for (int ck = 0; ck < 4; ++ck) {
        k_A<<<BNH_ / 256, 256>>>(inputs, w_in, b_in, res_w, res_b,
                                 gconv_w, gconv_b, ck, lefts[ck]);
        k_layer0<<<gl, 64>>>(gcn_adj_b, gcn_pea_b);
        k_layer1<<<gl, 64>>>(gcn_adj_b, gcn_pea_b);
        k_gate<<<BNH_ / 64 / 32, 128>>>(gate1_w, gate1_b, gate2_w, gate2_b,
                                        reduce_w, reduce_b, ck);
    }
    k_out<<<(B_ * N_) / 4, 256>>>(out_cw, out_cb, out_lw, out_lb, out);
}